// round 12
// baseline (speedup 1.0000x reference)
#include <cuda_runtime.h>
#include <cuda_bf16.h>
#include <mma.h>
#include <math.h>
#include <stdint.h>

using namespace nvcuda;

// Problem constants
#define BATCH 4
#define SEQ   2048
#define EMB   1024
#define HEADS 16
#define HD    64
#define MROWS (BATCH * SEQ)          // 8192
#define QKVN  (3 * EMB)              // 3072

// ---------------------------------------------------------------------------
// Device-global scratch
// ---------------------------------------------------------------------------
__device__ float g_q[BATCH * HEADS * SEQ * HD];   // [B,H,S,hd] fp32 (pre-rope)
__device__ float g_k[BATCH * HEADS * SEQ * HD];
__device__ float g_v[BATCH * HEADS * SEQ * HD];

// bf16 split operand buffers for GEMMs
__device__ __nv_bfloat16 g_ah[MROWS * EMB], g_al[MROWS * EMB];   // hidden
__device__ __nv_bfloat16 g_wh[QKVN * EMB],  g_wl[QKVN * EMB];    // qkv_w
__device__ __nv_bfloat16 g_ph[EMB * EMB],   g_pl[EMB * EMB];     // proj_w
__device__ __nv_bfloat16 g_aoh[MROWS * EMB], g_aol[MROWS * EMB]; // attn out

// bf16 split attention operands
__device__ __nv_bfloat16 g_qh[BATCH * HEADS * SEQ * HD], g_ql[BATCH * HEADS * SEQ * HD];
__device__ __nv_bfloat16 g_kh[BATCH * HEADS * SEQ * HD], g_kl[BATCH * HEADS * SEQ * HD];
__device__ __nv_bfloat16 g_vth[BATCH * HEADS * HD * SEQ], g_vtl[BATCH * HEADS * HD * SEQ]; // [B,H,hd,S]

// ---------------------------------------------------------------------------
// helpers
// ---------------------------------------------------------------------------
__device__ __forceinline__ uint32_t smem_u32(const void* p) {
    uint32_t a;
    asm("{ .reg .u64 t; cvta.to.shared.u64 t, %1; cvt.u32.u64 %0, t; }"
        : "=r"(a) : "l"(p));
    return a;
}
__device__ __forceinline__ void cp_async16(uint32_t dst, const void* src) {
    asm volatile("cp.async.cg.shared.global [%0], [%1], 16;"
                 :: "r"(dst), "l"(src) : "memory");
}
__device__ __forceinline__ void cp_commit() {
    asm volatile("cp.async.commit_group;" ::: "memory");
}
template <int N>
__device__ __forceinline__ void cp_wait() {
    asm volatile("cp.async.wait_group %0;" :: "n"(N) : "memory");
}
// D += A*B, m16n8k16 row.col bf16 -> f32
__device__ __forceinline__ void mma16816(float* d, const uint32_t* a,
                                         uint32_t b0, uint32_t b1) {
    asm volatile(
        "mma.sync.aligned.m16n8k16.row.col.f32.bf16.bf16.f32 "
        "{%0,%1,%2,%3}, {%4,%5,%6,%7}, {%8,%9}, {%0,%1,%2,%3};"
        : "+f"(d[0]), "+f"(d[1]), "+f"(d[2]), "+f"(d[3])
        : "r"(a[0]), "r"(a[1]), "r"(a[2]), "r"(a[3]), "r"(b0), "r"(b1));
}
// pack two f32 into bf16x2 (lo in low half)
__device__ __forceinline__ uint32_t pack_bf16x2(float lo, float hi) {
    uint32_t r;
    asm("cvt.rn.bf16x2.f32 %0, %1, %2;" : "=r"(r) : "f"(hi), "f"(lo));
    return r;
}
__device__ __forceinline__ float bres(float f) {
    return f - __bfloat162float(__float2bfloat16_rn(f));
}

// ---------------------------------------------------------------------------
// fp32 -> (bf16 hi, bf16 lo) split conversion.  WHICH: 0=hidden 1=qkv_w 2=proj_w
// ---------------------------------------------------------------------------
template <int WHICH>
__global__ __launch_bounds__(256)
void split_kernel(const float* __restrict__ x, int n4)
{
    __nv_bfloat16* hi = (WHICH == 0) ? g_ah : (WHICH == 1) ? g_wh : g_ph;
    __nv_bfloat16* lo = (WHICH == 0) ? g_al : (WHICH == 1) ? g_wl : g_pl;
    int i = blockIdx.x * 256 + threadIdx.x;
    if (i >= n4) return;
    float4 v = reinterpret_cast<const float4*>(x)[i];
    __nv_bfloat16 h0 = __float2bfloat16_rn(v.x);
    __nv_bfloat16 h1 = __float2bfloat16_rn(v.y);
    __nv_bfloat16 h2 = __float2bfloat16_rn(v.z);
    __nv_bfloat16 h3 = __float2bfloat16_rn(v.w);
    __nv_bfloat16 l0 = __float2bfloat16_rn(v.x - __bfloat162float(h0));
    __nv_bfloat16 l1 = __float2bfloat16_rn(v.y - __bfloat162float(h1));
    __nv_bfloat16 l2 = __float2bfloat16_rn(v.z - __bfloat162float(h2));
    __nv_bfloat16 l3 = __float2bfloat16_rn(v.w - __bfloat162float(h3));
    __nv_bfloat162* hp = reinterpret_cast<__nv_bfloat162*>(hi) + 2 * i;
    __nv_bfloat162* lp = reinterpret_cast<__nv_bfloat162*>(lo) + 2 * i;
    hp[0] = __halves2bfloat162(h0, h1);
    hp[1] = __halves2bfloat162(h2, h3);
    lp[0] = __halves2bfloat162(l0, l1);
    lp[1] = __halves2bfloat162(l2, l3);
}

// ---------------------------------------------------------------------------
// WMMA split-bf16 GEMM v2:  C[m,n] = sum_k A[m,k]*W[n,k] + bias[n]
// CTA tile 256(M)x128(N), 8 warps each 64x64, BK=32, 3-stage cp.async.
// MODE 1: A=g_ah/g_al, W=g_wh/g_wl, epilogue scatters into g_q/g_k/g_v.
// MODE 2: A=g_aoh/g_aol, W=g_ph/g_pl, epilogue writes C (+bias).
// ---------------------------------------------------------------------------
#define BK       32
#define LDS_AB   40                      // padded row length (elems)
#define A_EL     (256 * LDS_AB)          // elems per A matrix tile (hi or lo)
#define B_EL     (128 * LDS_AB)
#define STAGE_EL (2 * A_EL + 2 * B_EL)   // Ah, Al, Bh, Bl = 30720 elems
#define STAGE_B  (STAGE_EL * 2)          // 61440 bytes
#define NSTAGE   3
#define GSMEM    (NSTAGE * STAGE_B)      // 184320 bytes
#define EPI_LD   132

__device__ __forceinline__ void cp_chunk(
    uint32_t sbuf, int c, int tid,
    const __nv_bfloat16* Ah, const __nv_bfloat16* Al,
    const __nv_bfloat16* Bh, const __nv_bfloat16* Bl,
    int m0, int n0)
{
    const int k0 = c * BK;
    // A tiles: 1024 x 16B ops each (256 rows x 32 cols)
#pragma unroll
    for (int t = 0; t < 2; t++) {
        const __nv_bfloat16* src = t ? Al : Ah;
#pragma unroll
        for (int i = 0; i < 4; i++) {
            const int idx = tid + i * 256;       // 0..1023
            const int r   = idx >> 2;            // 0..255
            const int seg = idx & 3;
            cp_async16(sbuf + (t * A_EL + r * LDS_AB + seg * 8) * 2,
                       src + (size_t)(m0 + r) * EMB + k0 + seg * 8);
        }
    }
    // B tiles: 512 x 16B ops each (128 rows x 32 cols)
#pragma unroll
    for (int t = 0; t < 2; t++) {
        const __nv_bfloat16* src = t ? Bl : Bh;
#pragma unroll
        for (int i = 0; i < 2; i++) {
            const int idx = tid + i * 256;       // 0..511
            const int r   = idx >> 2;            // 0..127
            const int seg = idx & 3;
            cp_async16(sbuf + (2 * A_EL + t * B_EL + r * LDS_AB + seg * 8) * 2,
                       src + (size_t)(n0 + r) * EMB + k0 + seg * 8);
        }
    }
}

template <int MODE>
__global__ __launch_bounds__(256)
void gemm_wmma(const float* __restrict__ bias, float* __restrict__ C)
{
    extern __shared__ __align__(16) char smem[];
    const int tid  = threadIdx.x;
    const int wid  = tid >> 5;
    const int m0 = blockIdx.y * 256;
    const int n0 = blockIdx.x * 128;

    const __nv_bfloat16* Ah = (MODE == 1) ? g_ah : g_aoh;
    const __nv_bfloat16* Al = (MODE == 1) ? g_al : g_aol;
    const __nv_bfloat16* Bh = (MODE == 1) ? g_wh : g_ph;
    const __nv_bfloat16* Bl = (MODE == 1) ? g_wl : g_pl;

    const int warp_m = (wid & 3) * 64;   // 0,64,128,192
    const int warp_n = (wid >> 2) * 64;  // 0,64

    wmma::fragment<wmma::accumulator, 16, 16, 16, float> acc[4][4];
#pragma unroll
    for (int mt = 0; mt < 4; mt++)
#pragma unroll
        for (int nt = 0; nt < 4; nt++) wmma::fill_fragment(acc[mt][nt], 0.0f);

    const uint32_t sb = smem_u32(smem);
    cp_chunk(sb, 0, tid, Ah, Al, Bh, Bl, m0, n0);
    cp_commit();
    cp_chunk(sb + STAGE_B, 1, tid, Ah, Al, Bh, Bl, m0, n0);
    cp_commit();

    const int NCH = EMB / BK;   // 32
    int stage = 0;
    for (int c = 0; c < NCH; c++) {
        if (c + 2 < NCH) {
            int ps = stage + 2; if (ps >= NSTAGE) ps -= NSTAGE;
            cp_chunk(sb + ps * STAGE_B, c + 2, tid, Ah, Al, Bh, Bl, m0, n0);
            cp_commit();
            cp_wait<2>();
        } else if (c + 1 < NCH) {
            cp_wait<1>();
        } else {
            cp_wait<0>();
        }
        __syncthreads();

        const __nv_bfloat16* buf =
            reinterpret_cast<const __nv_bfloat16*>(smem + stage * STAGE_B);
        const __nv_bfloat16* sAh = buf;
        const __nv_bfloat16* sAl = buf + A_EL;
        const __nv_bfloat16* sBh = buf + 2 * A_EL;
        const __nv_bfloat16* sBl = buf + 2 * A_EL + B_EL;

#pragma unroll
        for (int ks = 0; ks < BK; ks += 16) {
            wmma::fragment<wmma::matrix_a, 16, 16, 16, __nv_bfloat16,
                           wmma::row_major> ah[4], al[4];
            wmma::fragment<wmma::matrix_b, 16, 16, 16, __nv_bfloat16,
                           wmma::col_major> bh[4], bl[4];
#pragma unroll
            for (int mt = 0; mt < 4; mt++) {
                wmma::load_matrix_sync(ah[mt],
                    sAh + (warp_m + mt * 16) * LDS_AB + ks, LDS_AB);
                wmma::load_matrix_sync(al[mt],
                    sAl + (warp_m + mt * 16) * LDS_AB + ks, LDS_AB);
            }
#pragma unroll
            for (int nt = 0; nt < 4; nt++) {
                wmma::load_matrix_sync(bh[nt],
                    sBh + (warp_n + nt * 16) * LDS_AB + ks, LDS_AB);
                wmma::load_matrix_sync(bl[nt],
                    sBl + (warp_n + nt * 16) * LDS_AB + ks, LDS_AB);
            }
#pragma unroll
            for (int mt = 0; mt < 4; mt++)
#pragma unroll
                for (int nt = 0; nt < 4; nt++) {
                    wmma::mma_sync(acc[mt][nt], ah[mt], bh[nt], acc[mt][nt]);
                    wmma::mma_sync(acc[mt][nt], ah[mt], bl[nt], acc[mt][nt]);
                    wmma::mma_sync(acc[mt][nt], al[mt], bh[nt], acc[mt][nt]);
                }
        }
        __syncthreads();
        if (++stage == NSTAGE) stage = 0;
    }

    // Epilogue: stage fp32 accumulators through smem, add bias, write out
    float* es = reinterpret_cast<float*>(smem);
#pragma unroll
    for (int mt = 0; mt < 4; mt++)
#pragma unroll
        for (int nt = 0; nt < 4; nt++)
            wmma::store_matrix_sync(
                es + (warp_m + mt * 16) * EPI_LD + warp_n + nt * 16,
                acc[mt][nt], EPI_LD, wmma::mem_row_major);
    __syncthreads();

#pragma unroll
    for (int i = 0; i < 32; i++) {
        const int idx  = tid + i * 256;      // over 256x32 float4 grid
        const int row  = idx >> 5;           // 0..255
        const int col4 = idx & 31;           // 0..31
        const int m = m0 + row;
        const int n = n0 + col4 * 4;
        const float4 bv = *reinterpret_cast<const float4*>(bias + n);
        float4 v;
        v.x = es[row * EPI_LD + col4 * 4 + 0] + bv.x;
        v.y = es[row * EPI_LD + col4 * 4 + 1] + bv.y;
        v.z = es[row * EPI_LD + col4 * 4 + 2] + bv.z;
        v.w = es[row * EPI_LD + col4 * 4 + 3] + bv.w;
        if (MODE == 1) {
            const int part = n >> 10;        // 0=q 1=k 2=v
            const int e    = n & 1023;
            const int h    = e >> 6;
            const int d    = e & 63;
            const int b    = m >> 11;
            const int s    = m & 2047;
            float* dst = (part == 0) ? g_q : (part == 1) ? g_k : g_v;
            *reinterpret_cast<float4*>(
                &dst[(((size_t)(b * HEADS + h) * SEQ) + s) * HD + d]) = v;
        } else {
            *reinterpret_cast<float4*>(&C[(size_t)m * EMB + n]) = v;
        }
    }
}

// ---------------------------------------------------------------------------
// RoPE + split: reads g_q/g_k fp32, writes bf16 hi/lo (q pre-scaled by 1/8).
// ---------------------------------------------------------------------------
__global__ __launch_bounds__(256)
void rope_split()
{
    const int warp = (blockIdx.x * blockDim.x + threadIdx.x) >> 5;
    const int lane = threadIdx.x & 31;
    if (warp >= BATCH * HEADS * SEQ) return;
    const int s = warp & (SEQ - 1);

    const float* qp = g_q + (size_t)warp * HD;
    const float* kp = g_k + (size_t)warp * HD;

    const float inv_freq = powf(10000.0f, -(float)(2 * lane) / (float)HD);
    float c, sn;
    sincosf((float)s * inv_freq, &sn, &c);

    float q1 = qp[lane], q2 = qp[lane + 32];
    float k1 = kp[lane], k2 = kp[lane + 32];
    float qa = (q1 * c - q2 * sn) * 0.125f;
    float qb = (q2 * c + q1 * sn) * 0.125f;
    float ka = k1 * c - k2 * sn;
    float kb = k2 * c + k1 * sn;

    const size_t base = (size_t)warp * HD;
    __nv_bfloat16 h;
    h = __float2bfloat16_rn(qa); g_qh[base + lane] = h;
    g_ql[base + lane] = __float2bfloat16_rn(qa - __bfloat162float(h));
    h = __float2bfloat16_rn(qb); g_qh[base + lane + 32] = h;
    g_ql[base + lane + 32] = __float2bfloat16_rn(qb - __bfloat162float(h));
    h = __float2bfloat16_rn(ka); g_kh[base + lane] = h;
    g_kl[base + lane] = __float2bfloat16_rn(ka - __bfloat162float(h));
    h = __float2bfloat16_rn(kb); g_kh[base + lane + 32] = h;
    g_kl[base + lane + 32] = __float2bfloat16_rn(kb - __bfloat162float(h));
}

// ---------------------------------------------------------------------------
// V prep: transpose [B,H,S,hd] fp32 -> [B,H,hd,S] bf16 hi/lo
// ---------------------------------------------------------------------------
__global__ __launch_bounds__(256)
void vprep()
{
    __shared__ float vs[64][65];
    const int tid  = threadIdx.x;
    const int sb   = blockIdx.x * 64;
    const int head = blockIdx.y;
    const float* V = g_v + ((size_t)head * SEQ + sb) * HD;
#pragma unroll
    for (int i = 0; i < 16; i++) {
        const int e = tid + i * 256;
        vs[e >> 6][e & 63] = V[(size_t)(e >> 6) * HD + (e & 63)];
    }
    __syncthreads();
    const int d  = tid >> 2;
    const int s4 = (tid & 3) * 16;
    __nv_bfloat16 hb[16], lb[16];
#pragma unroll
    for (int j = 0; j < 16; j++) {
        const float f = vs[s4 + j][d];
        const __nv_bfloat16 h = __float2bfloat16_rn(f);
        hb[j] = h;
        lb[j] = __float2bfloat16_rn(f - __bfloat162float(h));
    }
    const size_t base = (size_t)head * HD * SEQ + (size_t)d * SEQ + sb + s4;
    reinterpret_cast<uint4*>(g_vth + base)[0] = reinterpret_cast<uint4*>(hb)[0];
    reinterpret_cast<uint4*>(g_vth + base)[1] = reinterpret_cast<uint4*>(hb)[1];
    reinterpret_cast<uint4*>(g_vtl + base)[0] = reinterpret_cast<uint4*>(lb)[0];
    reinterpret_cast<uint4*>(g_vtl + base)[1] = reinterpret_cast<uint4*>(lb)[1];
}

// ---------------------------------------------------------------------------
// Tensor-core flash attention (unchanged from R11). grid=(SEQ/128, B*H).
// ---------------------------------------------------------------------------
#define AK_STR   72
#define ATILE_EL (64 * AK_STR)
#define ABUF_EL  (4 * ATILE_EL)
#define AT_SMEM  (2 * ABUF_EL * 2)      // 73728 bytes

__device__ __forceinline__ void attn_stage(uint32_t sb, int buf, int kb,
                                           size_t hbase, size_t vbase, int tid)
{
#pragma unroll
    for (int i = 0; i < 8; i++) {
        const int t  = i >> 1;
        const int r  = (tid >> 3) + 32 * (i & 1);
        const int ch = tid & 7;
        const __nv_bfloat16* src;
        if (t == 0)      src = g_kh  + hbase + (size_t)(kb * 64 + r) * HD + ch * 8;
        else if (t == 1) src = g_kl  + hbase + (size_t)(kb * 64 + r) * HD + ch * 8;
        else if (t == 2) src = g_vth + vbase + (size_t)r * SEQ + kb * 64 + ch * 8;
        else             src = g_vtl + vbase + (size_t)r * SEQ + kb * 64 + ch * 8;
        cp_async16(sb + (buf * ABUF_EL + t * ATILE_EL + r * AK_STR + ch * 8) * 2, src);
    }
}

__global__ __launch_bounds__(256)
void attn_mma()
{
    extern __shared__ __align__(16) __nv_bfloat16 sk[];
    const uint32_t sb = smem_u32(sk);
    const int tid  = threadIdx.x;
    const int wid  = tid >> 5;
    const int lane = tid & 31;
    const int gid  = lane >> 2;
    const int tidg = lane & 3;
    const int qb   = blockIdx.x;
    const int head = blockIdx.y;

    const size_t hbase = (size_t)head * SEQ * HD;
    const size_t vbase = (size_t)head * HD * SEQ;

    uint32_t qah[4][4], qal[4][4];
    {
        const int r0 = qb * 128 + wid * 16 + gid;
        const uint32_t* q0h = reinterpret_cast<const uint32_t*>(g_qh + hbase + (size_t)r0 * HD);
        const uint32_t* q1h = reinterpret_cast<const uint32_t*>(g_qh + hbase + (size_t)(r0 + 8) * HD);
        const uint32_t* q0l = reinterpret_cast<const uint32_t*>(g_ql + hbase + (size_t)r0 * HD);
        const uint32_t* q1l = reinterpret_cast<const uint32_t*>(g_ql + hbase + (size_t)(r0 + 8) * HD);
#pragma unroll
        for (int ks = 0; ks < 4; ks++) {
            qah[ks][0] = q0h[ks * 8 + tidg];
            qah[ks][1] = q1h[ks * 8 + tidg];
            qah[ks][2] = q0h[ks * 8 + tidg + 4];
            qah[ks][3] = q1h[ks * 8 + tidg + 4];
            qal[ks][0] = q0l[ks * 8 + tidg];
            qal[ks][1] = q1l[ks * 8 + tidg];
            qal[ks][2] = q0l[ks * 8 + tidg + 4];
            qal[ks][3] = q1l[ks * 8 + tidg + 4];
        }
    }

    float o[8][4];
#pragma unroll
    for (int nt = 0; nt < 8; nt++)
#pragma unroll
        for (int j = 0; j < 4; j++) o[nt][j] = 0.0f;
    float m0 = -1e30f, m1 = -1e30f, l0 = 0.0f, l1 = 0.0f;

    attn_stage(sb, 0, 0, hbase, vbase, tid);
    cp_commit();

    const int NKB = SEQ / 64;
    for (int kb = 0; kb < NKB; kb++) {
        if (kb + 1 < NKB) {
            attn_stage(sb, (kb + 1) & 1, kb + 1, hbase, vbase, tid);
            cp_commit();
            cp_wait<1>();
        } else {
            cp_wait<0>();
        }
        __syncthreads();

        const __nv_bfloat16* bs = sk + (kb & 1) * ABUF_EL;
        const __nv_bfloat16* Kh = bs;
        const __nv_bfloat16* Kl = bs + ATILE_EL;
        const __nv_bfloat16* Vh = bs + 2 * ATILE_EL;
        const __nv_bfloat16* Vl = bs + 3 * ATILE_EL;

        float s[8][4];
#pragma unroll
        for (int nt = 0; nt < 8; nt++)
#pragma unroll
            for (int j = 0; j < 4; j++) s[nt][j] = 0.0f;

#pragma unroll
        for (int ks = 0; ks < 4; ks++) {
#pragma unroll
            for (int nt = 0; nt < 8; nt++) {
                const uint32_t* krh = reinterpret_cast<const uint32_t*>(
                    Kh + (nt * 8 + gid) * AK_STR);
                const uint32_t* krl = reinterpret_cast<const uint32_t*>(
                    Kl + (nt * 8 + gid) * AK_STR);
                const uint32_t bh0 = krh[8 * ks + tidg];
                const uint32_t bh1 = krh[8 * ks + tidg + 4];
                const uint32_t bl0 = krl[8 * ks + tidg];
                const uint32_t bl1 = krl[8 * ks + tidg + 4];
                mma16816(s[nt], qah[ks], bh0, bh1);
                mma16816(s[nt], qah[ks], bl0, bl1);
                mma16816(s[nt], qal[ks], bh0, bh1);
            }
        }

        float mx0 = -1e30f, mx1 = -1e30f;
#pragma unroll
        for (int nt = 0; nt < 8; nt++) {
            mx0 = fmaxf(mx0, fmaxf(s[nt][0], s[nt][1]));
            mx1 = fmaxf(mx1, fmaxf(s[nt][2], s[nt][3]));
        }
        mx0 = fmaxf(mx0, __shfl_xor_sync(0xffffffffu, mx0, 1));
        mx0 = fmaxf(mx0, __shfl_xor_sync(0xffffffffu, mx0, 2));
        mx1 = fmaxf(mx1, __shfl_xor_sync(0xffffffffu, mx1, 1));
        mx1 = fmaxf(mx1, __shfl_xor_sync(0xffffffffu, mx1, 2));
        const float mn0 = fmaxf(m0, mx0), mn1 = fmaxf(m1, mx1);
        const float c0 = __expf(m0 - mn0), c1 = __expf(m1 - mn1);
        float rs0 = 0.0f, rs1 = 0.0f;
#pragma unroll
        for (int nt = 0; nt < 8; nt++) {
            s[nt][0] = __expf(s[nt][0] - mn0);
            s[nt][1] = __expf(s[nt][1] - mn0);
            s[nt][2] = __expf(s[nt][2] - mn1);
            s[nt][3] = __expf(s[nt][3] - mn1);
            rs0 += s[nt][0] + s[nt][1];
            rs1 += s[nt][2] + s[nt][3];
        }
        rs0 += __shfl_xor_sync(0xffffffffu, rs0, 1);
        rs0 += __shfl_xor_sync(0xffffffffu, rs0, 2);
        rs1 += __shfl_xor_sync(0xffffffffu, rs1, 1);
        rs1 += __shfl_xor_sync(0xffffffffu, rs1, 2);
        l0 = l0 * c0 + rs0;  l1 = l1 * c1 + rs1;
        m0 = mn0;  m1 = mn1;
#pragma unroll
        for (int nt = 0; nt < 8; nt++) {
            o[nt][0] *= c0; o[nt][1] *= c0;
            o[nt][2] *= c1; o[nt][3] *= c1;
        }

#pragma unroll
        for (int ks = 0; ks < 4; ks++) {
            uint32_t pah[4], pal[4];
            pah[0] = pack_bf16x2(s[2 * ks][0], s[2 * ks][1]);
            pah[1] = pack_bf16x2(s[2 * ks][2], s[2 * ks][3]);
            pah[2] = pack_bf16x2(s[2 * ks + 1][0], s[2 * ks + 1][1]);
            pah[3] = pack_bf16x2(s[2 * ks + 1][2], s[2 * ks + 1][3]);
            pal[0] = pack_bf16x2(bres(s[2 * ks][0]), bres(s[2 * ks][1]));
            pal[1] = pack_bf16x2(bres(s[2 * ks][2]), bres(s[2 * ks][3]));
            pal[2] = pack_bf16x2(bres(s[2 * ks + 1][0]), bres(s[2 * ks + 1][1]));
            pal[3] = pack_bf16x2(bres(s[2 * ks + 1][2]), bres(s[2 * ks + 1][3]));
#pragma unroll
            for (int nt = 0; nt < 8; nt++) {
                const uint32_t* vrh = reinterpret_cast<const uint32_t*>(
                    Vh + (nt * 8 + gid) * AK_STR);
                const uint32_t* vrl = reinterpret_cast<const uint32_t*>(
                    Vl + (nt * 8 + gid) * AK_STR);
                const uint32_t bh0 = vrh[8 * ks + tidg];
                const uint32_t bh1 = vrh[8 * ks + tidg + 4];
                const uint32_t bl0 = vrl[8 * ks + tidg];
                const uint32_t bl1 = vrl[8 * ks + tidg + 4];
                mma16816(o[nt], pah, bh0, bh1);
                mma16816(o[nt], pah, bl0, bl1);
                mma16816(o[nt], pal, bh0, bh1);
            }
        }
        __syncthreads();
    }

    const float i0 = 1.0f / l0, i1 = 1.0f / l1;
    const int b = head >> 4, h = head & 15;
    const int s0 = qb * 128 + wid * 16;
#pragma unroll
    for (int nt = 0; nt < 8; nt++) {
        const float f0 = o[nt][0] * i0, f1 = o[nt][1] * i0;
        const float f2 = o[nt][2] * i1, f3 = o[nt][3] * i1;
        const size_t base0 = (size_t)(b * SEQ + s0 + gid) * EMB +
                             h * 64 + nt * 8 + 2 * tidg;
        const size_t base1 = (size_t)(b * SEQ + s0 + gid + 8) * EMB +
                             h * 64 + nt * 8 + 2 * tidg;
        *reinterpret_cast<uint32_t*>(g_aoh + base0) = pack_bf16x2(f0, f1);
        *reinterpret_cast<uint32_t*>(g_aol + base0) = pack_bf16x2(bres(f0), bres(f1));
        *reinterpret_cast<uint32_t*>(g_aoh + base1) = pack_bf16x2(f2, f3);
        *reinterpret_cast<uint32_t*>(g_aol + base1) = pack_bf16x2(bres(f2), bres(f3));
    }
}

// ---------------------------------------------------------------------------
extern "C" void kernel_launch(void* const* d_in, const int* in_sizes, int n_in,
                              void* d_out, int out_size)
{
    const float* hidden = (const float*)d_in[0];
    const float* qkv_w  = (const float*)d_in[1];
    const float* qkv_b  = (const float*)d_in[2];
    const float* proj_w = (const float*)d_in[3];
    const float* proj_b = (const float*)d_in[4];
    float* out = (float*)d_out;

    // 0) split fp32 -> bf16 hi/lo
    split_kernel<0><<<(MROWS * EMB / 4 + 255) / 256, 256>>>(hidden, MROWS * EMB / 4);
    split_kernel<1><<<(QKVN * EMB / 4 + 255) / 256, 256>>>(qkv_w, QKVN * EMB / 4);
    split_kernel<2><<<(EMB * EMB / 4 + 255) / 256, 256>>>(proj_w, EMB * EMB / 4);

    // 1) QKV GEMM (WMMA split bf16, 256x128 tiles) + scatter to q/k/v fp32
    cudaFuncSetAttribute(gemm_wmma<1>,
                         cudaFuncAttributeMaxDynamicSharedMemorySize, GSMEM);
    gemm_wmma<1><<<dim3(QKVN / 128, MROWS / 256), 256, GSMEM>>>(qkv_b, nullptr);

    // 2) RoPE + bf16 split of q,k ; transpose+split of v
    rope_split<<<(BATCH * HEADS * SEQ + 7) / 8, 256>>>();
    vprep<<<dim3(SEQ / 64, BATCH * HEADS), 256>>>();

    // 3) tensor-core flash attention (split bf16), writes split output
    cudaFuncSetAttribute(attn_mma,
                         cudaFuncAttributeMaxDynamicSharedMemorySize, AT_SMEM);
    attn_mma<<<dim3(SEQ / 128, BATCH * HEADS), 256, AT_SMEM>>>();

    // 4) output projection (WMMA split bf16)
    cudaFuncSetAttribute(gemm_wmma<2>,
                         cudaFuncAttributeMaxDynamicSharedMemorySize, GSMEM);
    gemm_wmma<2><<<dim3(EMB / 128, MROWS / 256), 256, GSMEM>>>(proj_b, out);
}

// round 13
// speedup vs baseline: 1.0613x; 1.0613x over previous
#include <cuda_runtime.h>
#include <cuda_bf16.h>
#include <mma.h>
#include <math.h>
#include <stdint.h>

using namespace nvcuda;

// Problem constants
#define BATCH 4
#define SEQ   2048
#define EMB   1024
#define HEADS 16
#define HD    64
#define MROWS (BATCH * SEQ)          // 8192
#define QKVN  (3 * EMB)              // 3072

// ---------------------------------------------------------------------------
// Device-global scratch
// ---------------------------------------------------------------------------
// bf16 split operand buffers for GEMMs
__device__ __nv_bfloat16 g_ah[MROWS * EMB], g_al[MROWS * EMB];   // hidden
__device__ __nv_bfloat16 g_wh[QKVN * EMB],  g_wl[QKVN * EMB];    // qkv_w
__device__ __nv_bfloat16 g_ph[EMB * EMB],   g_pl[EMB * EMB];     // proj_w
__device__ __nv_bfloat16 g_aoh[MROWS * EMB], g_aol[MROWS * EMB]; // attn out

// bf16 split attention operands (produced directly by gemm1 fused epilogue)
__device__ __nv_bfloat16 g_qh[BATCH * HEADS * SEQ * HD], g_ql[BATCH * HEADS * SEQ * HD];
__device__ __nv_bfloat16 g_kh[BATCH * HEADS * SEQ * HD], g_kl[BATCH * HEADS * SEQ * HD];
__device__ __nv_bfloat16 g_vth[BATCH * HEADS * HD * SEQ], g_vtl[BATCH * HEADS * HD * SEQ]; // [B,H,hd,S]

// RoPE cos/sin table [SEQ][32]
__device__ float g_cos[SEQ * 32], g_sin[SEQ * 32];

// ---------------------------------------------------------------------------
// helpers
// ---------------------------------------------------------------------------
__device__ __forceinline__ uint32_t smem_u32(const void* p) {
    uint32_t a;
    asm("{ .reg .u64 t; cvta.to.shared.u64 t, %1; cvt.u32.u64 %0, t; }"
        : "=r"(a) : "l"(p));
    return a;
}
__device__ __forceinline__ void cp_async16(uint32_t dst, const void* src) {
    asm volatile("cp.async.cg.shared.global [%0], [%1], 16;"
                 :: "r"(dst), "l"(src) : "memory");
}
__device__ __forceinline__ void cp_commit() {
    asm volatile("cp.async.commit_group;" ::: "memory");
}
template <int N>
__device__ __forceinline__ void cp_wait() {
    asm volatile("cp.async.wait_group %0;" :: "n"(N) : "memory");
}
// D += A*B, m16n8k16 row.col bf16 -> f32
__device__ __forceinline__ void mma16816(float* d, const uint32_t* a,
                                         uint32_t b0, uint32_t b1) {
    asm volatile(
        "mma.sync.aligned.m16n8k16.row.col.f32.bf16.bf16.f32 "
        "{%0,%1,%2,%3}, {%4,%5,%6,%7}, {%8,%9}, {%0,%1,%2,%3};"
        : "+f"(d[0]), "+f"(d[1]), "+f"(d[2]), "+f"(d[3])
        : "r"(a[0]), "r"(a[1]), "r"(a[2]), "r"(a[3]), "r"(b0), "r"(b1));
}
// pack two f32 into bf16x2 (first arg in low half)
__device__ __forceinline__ uint32_t pack_bf16x2(float lo, float hi) {
    uint32_t r;
    asm("cvt.rn.bf16x2.f32 %0, %1, %2;" : "=r"(r) : "f"(hi), "f"(lo));
    return r;
}
__device__ __forceinline__ float bres(float f) {
    return f - __bfloat162float(__float2bfloat16_rn(f));
}

// ---------------------------------------------------------------------------
// RoPE cos/sin table
// ---------------------------------------------------------------------------
__global__ __launch_bounds__(256)
void costab_kernel()
{
    const int i = blockIdx.x * 256 + threadIdx.x;
    if (i >= SEQ * 32) return;
    const int s = i >> 5, j = i & 31;
    const float invf = powf(10000.0f, -(float)(2 * j) / 64.0f);
    float c, sn;
    sincosf((float)s * invf, &sn, &c);
    g_cos[i] = c;
    g_sin[i] = sn;
}

// ---------------------------------------------------------------------------
// fp32 -> (bf16 hi, bf16 lo) split conversion.  WHICH: 0=hidden 1=qkv_w 2=proj_w
// ---------------------------------------------------------------------------
template <int WHICH>
__global__ __launch_bounds__(256)
void split_kernel(const float* __restrict__ x, int n4)
{
    __nv_bfloat16* hi = (WHICH == 0) ? g_ah : (WHICH == 1) ? g_wh : g_ph;
    __nv_bfloat16* lo = (WHICH == 0) ? g_al : (WHICH == 1) ? g_wl : g_pl;
    int i = blockIdx.x * 256 + threadIdx.x;
    if (i >= n4) return;
    float4 v = reinterpret_cast<const float4*>(x)[i];
    __nv_bfloat16 h0 = __float2bfloat16_rn(v.x);
    __nv_bfloat16 h1 = __float2bfloat16_rn(v.y);
    __nv_bfloat16 h2 = __float2bfloat16_rn(v.z);
    __nv_bfloat16 h3 = __float2bfloat16_rn(v.w);
    __nv_bfloat16 l0 = __float2bfloat16_rn(v.x - __bfloat162float(h0));
    __nv_bfloat16 l1 = __float2bfloat16_rn(v.y - __bfloat162float(h1));
    __nv_bfloat16 l2 = __float2bfloat16_rn(v.z - __bfloat162float(h2));
    __nv_bfloat16 l3 = __float2bfloat16_rn(v.w - __bfloat162float(h3));
    __nv_bfloat162* hp = reinterpret_cast<__nv_bfloat162*>(hi) + 2 * i;
    __nv_bfloat162* lp = reinterpret_cast<__nv_bfloat162*>(lo) + 2 * i;
    hp[0] = __halves2bfloat162(h0, h1);
    hp[1] = __halves2bfloat162(h2, h3);
    lp[0] = __halves2bfloat162(l0, l1);
    lp[1] = __halves2bfloat162(l2, l3);
}

// ---------------------------------------------------------------------------
// WMMA split-bf16 GEMM (R11 config: CTA 128x128, BK=32, 2-stage, 8 warps 32x64)
// MODE 1: A=g_ah/g_al, W=g_wh/g_wl. FUSED epilogue: RoPE+split for q/k,
//         transpose+split for v — writes g_qh/ql, g_kh/kl, g_vth/vtl directly.
// MODE 2: A=g_aoh/g_aol, W=g_ph/g_pl, epilogue writes C (+bias).
// ---------------------------------------------------------------------------
#define BK      32
#define LDS_AB  40
#define TILE_EL (128 * LDS_AB)
#define TILE_B  (TILE_EL * 2)
#define BUF_B   (4 * TILE_B)
#define GSMEM   (2 * BUF_B)
#define EPI_LD  132

__device__ __forceinline__ void cp_chunk(
    uint32_t sbuf, int c, int tid,
    const __nv_bfloat16* Ah, const __nv_bfloat16* Al,
    const __nv_bfloat16* Bh, const __nv_bfloat16* Bl,
    int m0, int n0)
{
    const int k0 = c * BK;
    const __nv_bfloat16* srcs[4] = {Ah, Al, Bh, Bl};
#pragma unroll
    for (int t = 0; t < 4; t++) {
        const int row0 = (t < 2) ? m0 : n0;
        const __nv_bfloat16* src = srcs[t];
#pragma unroll
        for (int i = 0; i < 2; i++) {
            const int idx = tid + i * 256;
            const int r   = idx >> 2;
            const int seg = idx & 3;
            cp_async16(sbuf + t * TILE_B + (r * LDS_AB + seg * 8) * 2,
                       src + (size_t)(row0 + r) * EMB + k0 + seg * 8);
        }
    }
}

template <int MODE>
__global__ __launch_bounds__(256)
void gemm_wmma(const float* __restrict__ bias, float* __restrict__ C)
{
    extern __shared__ __align__(16) char smem[];
    const int tid  = threadIdx.x;
    const int wid  = tid >> 5;
    const int m0 = blockIdx.y * 128;
    const int n0 = blockIdx.x * 128;

    const __nv_bfloat16* Ah = (MODE == 1) ? g_ah : g_aoh;
    const __nv_bfloat16* Al = (MODE == 1) ? g_al : g_aol;
    const __nv_bfloat16* Bh = (MODE == 1) ? g_wh : g_ph;
    const __nv_bfloat16* Bl = (MODE == 1) ? g_wl : g_pl;

    const int warp_m = (wid & 3) * 32;
    const int warp_n = (wid >> 2) * 64;

    wmma::fragment<wmma::accumulator, 16, 16, 16, float> acc[2][4];
#pragma unroll
    for (int mt = 0; mt < 2; mt++)
#pragma unroll
        for (int nt = 0; nt < 4; nt++) wmma::fill_fragment(acc[mt][nt], 0.0f);

    const uint32_t sb = smem_u32(smem);
    cp_chunk(sb, 0, tid, Ah, Al, Bh, Bl, m0, n0);
    cp_commit();

    const int NCH = EMB / BK;
    for (int c = 0; c < NCH; c++) {
        if (c + 1 < NCH) {
            cp_chunk(sb + ((c + 1) & 1) * BUF_B, c + 1, tid, Ah, Al, Bh, Bl, m0, n0);
            cp_commit();
            cp_wait<1>();
        } else {
            cp_wait<0>();
        }
        __syncthreads();

        const __nv_bfloat16* buf =
            reinterpret_cast<const __nv_bfloat16*>(smem + (c & 1) * BUF_B);
        const __nv_bfloat16* sAh = buf;
        const __nv_bfloat16* sAl = buf + TILE_EL;
        const __nv_bfloat16* sBh = buf + 2 * TILE_EL;
        const __nv_bfloat16* sBl = buf + 3 * TILE_EL;

#pragma unroll
        for (int ks = 0; ks < BK; ks += 16) {
            wmma::fragment<wmma::matrix_a, 16, 16, 16, __nv_bfloat16,
                           wmma::row_major> ah[2], al[2];
            wmma::fragment<wmma::matrix_b, 16, 16, 16, __nv_bfloat16,
                           wmma::col_major> bh[4], bl[4];
#pragma unroll
            for (int mt = 0; mt < 2; mt++) {
                wmma::load_matrix_sync(ah[mt],
                    sAh + (warp_m + mt * 16) * LDS_AB + ks, LDS_AB);
                wmma::load_matrix_sync(al[mt],
                    sAl + (warp_m + mt * 16) * LDS_AB + ks, LDS_AB);
            }
#pragma unroll
            for (int nt = 0; nt < 4; nt++) {
                wmma::load_matrix_sync(bh[nt],
                    sBh + (warp_n + nt * 16) * LDS_AB + ks, LDS_AB);
                wmma::load_matrix_sync(bl[nt],
                    sBl + (warp_n + nt * 16) * LDS_AB + ks, LDS_AB);
            }
#pragma unroll
            for (int mt = 0; mt < 2; mt++)
#pragma unroll
                for (int nt = 0; nt < 4; nt++) {
                    wmma::mma_sync(acc[mt][nt], ah[mt], bh[nt], acc[mt][nt]);
                    wmma::mma_sync(acc[mt][nt], ah[mt], bl[nt], acc[mt][nt]);
                    wmma::mma_sync(acc[mt][nt], al[mt], bh[nt], acc[mt][nt]);
                }
        }
        __syncthreads();
    }

    // Stage fp32 accumulators in smem
    float* es = reinterpret_cast<float*>(smem);
#pragma unroll
    for (int mt = 0; mt < 2; mt++)
#pragma unroll
        for (int nt = 0; nt < 4; nt++)
            wmma::store_matrix_sync(
                es + (warp_m + mt * 16) * EPI_LD + warp_n + nt * 16,
                acc[mt][nt], EPI_LD, wmma::mem_row_major);
    __syncthreads();

    if (MODE == 2) {
#pragma unroll
        for (int i = 0; i < 16; i++) {
            const int idx  = tid + i * 256;
            const int row  = idx >> 5;
            const int col4 = idx & 31;
            const int m = m0 + row;
            const int n = n0 + col4 * 4;
            const float4 bv = *reinterpret_cast<const float4*>(bias + n);
            float4 v;
            v.x = es[row * EPI_LD + col4 * 4 + 0] + bv.x;
            v.y = es[row * EPI_LD + col4 * 4 + 1] + bv.y;
            v.z = es[row * EPI_LD + col4 * 4 + 2] + bv.z;
            v.w = es[row * EPI_LD + col4 * 4 + 3] + bv.w;
            *reinterpret_cast<float4*>(&C[(size_t)m * EMB + n]) = v;
        }
        return;
    }

    // ---- MODE 1 fused epilogue ----
    const int part = n0 >> 10;           // 0=q 1=k 2=v (uniform per block)
    if (part < 2) {
        // RoPE + split for q/k
        __nv_bfloat16* dh = part ? g_kh : g_qh;
        __nv_bfloat16* dl = part ? g_kl : g_ql;
        const float qscale = part ? 1.0f : 0.125f;
#pragma unroll
        for (int i = 0; i < 16; i++) {
            const int idx  = tid + i * 256;
            const int row  = idx >> 5;
            const int col4 = idx & 31;
            const int cc   = col4 * 4;          // 0..124, within-tile column
            const int n    = n0 + cc;
            const int m    = m0 + row;
            const int h    = (n & 1023) >> 6;
            const int d    = n & 63;            // group of 4 within one half
            const int b    = m >> 11, s = m & 2047;
            const int dp   = d & 31;

            const float4 bv  = *reinterpret_cast<const float4*>(bias + n);
            const float4 bvp = *reinterpret_cast<const float4*>(bias + (n ^ 32));
            const float4 cv  = *reinterpret_cast<const float4*>(g_cos + s * 32 + dp);
            const float4 sv  = *reinterpret_cast<const float4*>(g_sin + s * 32 + dp);
            const float bvx[4]  = {bv.x, bv.y, bv.z, bv.w};
            const float bvpx[4] = {bvp.x, bvp.y, bvp.z, bvp.w};
            const float cvx[4]  = {cv.x, cv.y, cv.z, cv.w};
            const float svx[4]  = {sv.x, sv.y, sv.z, sv.w};

            const float sgn = (d < 32) ? -1.0f : 1.0f;
            uint32_t hw[2], lw[2];
#pragma unroll
            for (int p2 = 0; p2 < 2; p2++) {
                float f[2];
#pragma unroll
                for (int q2 = 0; q2 < 2; q2++) {
                    const int j2 = p2 * 2 + q2;
                    const float x  = es[row * EPI_LD + cc + j2] + bvx[j2];
                    const float xp = es[row * EPI_LD + ((cc + j2) ^ 32)] + bvpx[j2];
                    f[q2] = (x * cvx[j2] + sgn * xp * svx[j2]) * qscale;
                }
                hw[p2] = pack_bf16x2(f[0], f[1]);
                lw[p2] = pack_bf16x2(bres(f[0]), bres(f[1]));
            }
            const size_t base = ((size_t)(b * HEADS + h) * SEQ + s) * HD + d;
            *reinterpret_cast<uint2*>(dh + base) = make_uint2(hw[0], hw[1]);
            *reinterpret_cast<uint2*>(dl + base) = make_uint2(lw[0], lw[1]);
        }
    } else {
        // V: transpose + split.  thread -> (d_loc 0..127, half 0..1), 64 s each
        const int dloc = tid & 127;
        const int half = tid >> 7;
        const int h    = ((n0 & 1023) >> 6) + (dloc >> 6);
        const int d    = dloc & 63;
        const int b    = m0 >> 11;
        const int sbase = (m0 & 2047) + half * 64;
        const float bvv = bias[n0 + dloc];
        const size_t vb = ((size_t)(b * HEADS + h) * HD + d) * SEQ + sbase;
#pragma unroll
        for (int jj = 0; jj < 8; jj++) {
            uint32_t hw[4], lw[4];
#pragma unroll
            for (int j2 = 0; j2 < 4; j2++) {
                const float f0 = es[(half * 64 + jj * 8 + 2 * j2)     * EPI_LD + dloc] + bvv;
                const float f1 = es[(half * 64 + jj * 8 + 2 * j2 + 1) * EPI_LD + dloc] + bvv;
                hw[j2] = pack_bf16x2(f0, f1);
                lw[j2] = pack_bf16x2(bres(f0), bres(f1));
            }
            *reinterpret_cast<uint4*>(g_vth + vb + jj * 8) =
                make_uint4(hw[0], hw[1], hw[2], hw[3]);
            *reinterpret_cast<uint4*>(g_vtl + vb + jj * 8) =
                make_uint4(lw[0], lw[1], lw[2], lw[3]);
        }
    }
}

// ---------------------------------------------------------------------------
// Tensor-core flash attention (unchanged from R11). grid=(SEQ/128, B*H).
// ---------------------------------------------------------------------------
#define AK_STR   72
#define ATILE_EL (64 * AK_STR)
#define ABUF_EL  (4 * ATILE_EL)
#define AT_SMEM  (2 * ABUF_EL * 2)      // 73728 bytes

__device__ __forceinline__ void attn_stage(uint32_t sb, int buf, int kb,
                                           size_t hbase, size_t vbase, int tid)
{
#pragma unroll
    for (int i = 0; i < 8; i++) {
        const int t  = i >> 1;
        const int r  = (tid >> 3) + 32 * (i & 1);
        const int ch = tid & 7;
        const __nv_bfloat16* src;
        if (t == 0)      src = g_kh  + hbase + (size_t)(kb * 64 + r) * HD + ch * 8;
        else if (t == 1) src = g_kl  + hbase + (size_t)(kb * 64 + r) * HD + ch * 8;
        else if (t == 2) src = g_vth + vbase + (size_t)r * SEQ + kb * 64 + ch * 8;
        else             src = g_vtl + vbase + (size_t)r * SEQ + kb * 64 + ch * 8;
        cp_async16(sb + (buf * ABUF_EL + t * ATILE_EL + r * AK_STR + ch * 8) * 2, src);
    }
}

__global__ __launch_bounds__(256)
void attn_mma()
{
    extern __shared__ __align__(16) __nv_bfloat16 sk[];
    const uint32_t sb = smem_u32(sk);
    const int tid  = threadIdx.x;
    const int wid  = tid >> 5;
    const int lane = tid & 31;
    const int gid  = lane >> 2;
    const int tidg = lane & 3;
    const int qb   = blockIdx.x;
    const int head = blockIdx.y;

    const size_t hbase = (size_t)head * SEQ * HD;
    const size_t vbase = (size_t)head * HD * SEQ;

    uint32_t qah[4][4], qal[4][4];
    {
        const int r0 = qb * 128 + wid * 16 + gid;
        const uint32_t* q0h = reinterpret_cast<const uint32_t*>(g_qh + hbase + (size_t)r0 * HD);
        const uint32_t* q1h = reinterpret_cast<const uint32_t*>(g_qh + hbase + (size_t)(r0 + 8) * HD);
        const uint32_t* q0l = reinterpret_cast<const uint32_t*>(g_ql + hbase + (size_t)r0 * HD);
        const uint32_t* q1l = reinterpret_cast<const uint32_t*>(g_ql + hbase + (size_t)(r0 + 8) * HD);
#pragma unroll
        for (int ks = 0; ks < 4; ks++) {
            qah[ks][0] = q0h[ks * 8 + tidg];
            qah[ks][1] = q1h[ks * 8 + tidg];
            qah[ks][2] = q0h[ks * 8 + tidg + 4];
            qah[ks][3] = q1h[ks * 8 + tidg + 4];
            qal[ks][0] = q0l[ks * 8 + tidg];
            qal[ks][1] = q1l[ks * 8 + tidg];
            qal[ks][2] = q0l[ks * 8 + tidg + 4];
            qal[ks][3] = q1l[ks * 8 + tidg + 4];
        }
    }

    float o[8][4];
#pragma unroll
    for (int nt = 0; nt < 8; nt++)
#pragma unroll
        for (int j = 0; j < 4; j++) o[nt][j] = 0.0f;
    float m0 = -1e30f, m1 = -1e30f, l0 = 0.0f, l1 = 0.0f;

    attn_stage(sb, 0, 0, hbase, vbase, tid);
    cp_commit();

    const int NKB = SEQ / 64;
    for (int kb = 0; kb < NKB; kb++) {
        if (kb + 1 < NKB) {
            attn_stage(sb, (kb + 1) & 1, kb + 1, hbase, vbase, tid);
            cp_commit();
            cp_wait<1>();
        } else {
            cp_wait<0>();
        }
        __syncthreads();

        const __nv_bfloat16* bs = sk + (kb & 1) * ABUF_EL;
        const __nv_bfloat16* Kh = bs;
        const __nv_bfloat16* Kl = bs + ATILE_EL;
        const __nv_bfloat16* Vh = bs + 2 * ATILE_EL;
        const __nv_bfloat16* Vl = bs + 3 * ATILE_EL;

        float s[8][4];
#pragma unroll
        for (int nt = 0; nt < 8; nt++)
#pragma unroll
            for (int j = 0; j < 4; j++) s[nt][j] = 0.0f;

#pragma unroll
        for (int ks = 0; ks < 4; ks++) {
#pragma unroll
            for (int nt = 0; nt < 8; nt++) {
                const uint32_t* krh = reinterpret_cast<const uint32_t*>(
                    Kh + (nt * 8 + gid) * AK_STR);
                const uint32_t* krl = reinterpret_cast<const uint32_t*>(
                    Kl + (nt * 8 + gid) * AK_STR);
                const uint32_t bh0 = krh[8 * ks + tidg];
                const uint32_t bh1 = krh[8 * ks + tidg + 4];
                const uint32_t bl0 = krl[8 * ks + tidg];
                const uint32_t bl1 = krl[8 * ks + tidg + 4];
                mma16816(s[nt], qah[ks], bh0, bh1);
                mma16816(s[nt], qah[ks], bl0, bl1);
                mma16816(s[nt], qal[ks], bh0, bh1);
            }
        }

        float mx0 = -1e30f, mx1 = -1e30f;
#pragma unroll
        for (int nt = 0; nt < 8; nt++) {
            mx0 = fmaxf(mx0, fmaxf(s[nt][0], s[nt][1]));
            mx1 = fmaxf(mx1, fmaxf(s[nt][2], s[nt][3]));
        }
        mx0 = fmaxf(mx0, __shfl_xor_sync(0xffffffffu, mx0, 1));
        mx0 = fmaxf(mx0, __shfl_xor_sync(0xffffffffu, mx0, 2));
        mx1 = fmaxf(mx1, __shfl_xor_sync(0xffffffffu, mx1, 1));
        mx1 = fmaxf(mx1, __shfl_xor_sync(0xffffffffu, mx1, 2));
        const float mn0 = fmaxf(m0, mx0), mn1 = fmaxf(m1, mx1);
        const float c0 = __expf(m0 - mn0), c1 = __expf(m1 - mn1);
        float rs0 = 0.0f, rs1 = 0.0f;
#pragma unroll
        for (int nt = 0; nt < 8; nt++) {
            s[nt][0] = __expf(s[nt][0] - mn0);
            s[nt][1] = __expf(s[nt][1] - mn0);
            s[nt][2] = __expf(s[nt][2] - mn1);
            s[nt][3] = __expf(s[nt][3] - mn1);
            rs0 += s[nt][0] + s[nt][1];
            rs1 += s[nt][2] + s[nt][3];
        }
        rs0 += __shfl_xor_sync(0xffffffffu, rs0, 1);
        rs0 += __shfl_xor_sync(0xffffffffu, rs0, 2);
        rs1 += __shfl_xor_sync(0xffffffffu, rs1, 1);
        rs1 += __shfl_xor_sync(0xffffffffu, rs1, 2);
        l0 = l0 * c0 + rs0;  l1 = l1 * c1 + rs1;
        m0 = mn0;  m1 = mn1;
#pragma unroll
        for (int nt = 0; nt < 8; nt++) {
            o[nt][0] *= c0; o[nt][1] *= c0;
            o[nt][2] *= c1; o[nt][3] *= c1;
        }

#pragma unroll
        for (int ks = 0; ks < 4; ks++) {
            uint32_t pah[4], pal[4];
            pah[0] = pack_bf16x2(s[2 * ks][0], s[2 * ks][1]);
            pah[1] = pack_bf16x2(s[2 * ks][2], s[2 * ks][3]);
            pah[2] = pack_bf16x2(s[2 * ks + 1][0], s[2 * ks + 1][1]);
            pah[3] = pack_bf16x2(s[2 * ks + 1][2], s[2 * ks + 1][3]);
            pal[0] = pack_bf16x2(bres(s[2 * ks][0]), bres(s[2 * ks][1]));
            pal[1] = pack_bf16x2(bres(s[2 * ks][2]), bres(s[2 * ks][3]));
            pal[2] = pack_bf16x2(bres(s[2 * ks + 1][0]), bres(s[2 * ks + 1][1]));
            pal[3] = pack_bf16x2(bres(s[2 * ks + 1][2]), bres(s[2 * ks + 1][3]));
#pragma unroll
            for (int nt = 0; nt < 8; nt++) {
                const uint32_t* vrh = reinterpret_cast<const uint32_t*>(
                    Vh + (nt * 8 + gid) * AK_STR);
                const uint32_t* vrl = reinterpret_cast<const uint32_t*>(
                    Vl + (nt * 8 + gid) * AK_STR);
                const uint32_t bh0 = vrh[8 * ks + tidg];
                const uint32_t bh1 = vrh[8 * ks + tidg + 4];
                const uint32_t bl0 = vrl[8 * ks + tidg];
                const uint32_t bl1 = vrl[8 * ks + tidg + 4];
                mma16816(o[nt], pah, bh0, bh1);
                mma16816(o[nt], pah, bl0, bl1);
                mma16816(o[nt], pal, bh0, bh1);
            }
        }
        __syncthreads();
    }

    const float i0 = 1.0f / l0, i1 = 1.0f / l1;
    const int b = head >> 4, h = head & 15;
    const int s0 = qb * 128 + wid * 16;
#pragma unroll
    for (int nt = 0; nt < 8; nt++) {
        const float f0 = o[nt][0] * i0, f1 = o[nt][1] * i0;
        const float f2 = o[nt][2] * i1, f3 = o[nt][3] * i1;
        const size_t base0 = (size_t)(b * SEQ + s0 + gid) * EMB +
                             h * 64 + nt * 8 + 2 * tidg;
        const size_t base1 = (size_t)(b * SEQ + s0 + gid + 8) * EMB +
                             h * 64 + nt * 8 + 2 * tidg;
        *reinterpret_cast<uint32_t*>(g_aoh + base0) = pack_bf16x2(f0, f1);
        *reinterpret_cast<uint32_t*>(g_aol + base0) = pack_bf16x2(bres(f0), bres(f1));
        *reinterpret_cast<uint32_t*>(g_aoh + base1) = pack_bf16x2(f2, f3);
        *reinterpret_cast<uint32_t*>(g_aol + base1) = pack_bf16x2(bres(f2), bres(f3));
    }
}

// ---------------------------------------------------------------------------
extern "C" void kernel_launch(void* const* d_in, const int* in_sizes, int n_in,
                              void* d_out, int out_size)
{
    const float* hidden = (const float*)d_in[0];
    const float* qkv_w  = (const float*)d_in[1];
    const float* qkv_b  = (const float*)d_in[2];
    const float* proj_w = (const float*)d_in[3];
    const float* proj_b = (const float*)d_in[4];
    float* out = (float*)d_out;

    // 0) cos/sin table + splits fp32 -> bf16 hi/lo
    costab_kernel<<<(SEQ * 32 + 255) / 256, 256>>>();
    split_kernel<0><<<(MROWS * EMB / 4 + 255) / 256, 256>>>(hidden, MROWS * EMB / 4);
    split_kernel<1><<<(QKVN * EMB / 4 + 255) / 256, 256>>>(qkv_w, QKVN * EMB / 4);
    split_kernel<2><<<(EMB * EMB / 4 + 255) / 256, 256>>>(proj_w, EMB * EMB / 4);

    // 1) QKV GEMM with fused RoPE/split/V-transpose epilogue
    cudaFuncSetAttribute(gemm_wmma<1>,
                         cudaFuncAttributeMaxDynamicSharedMemorySize, GSMEM);
    gemm_wmma<1><<<dim3(QKVN / 128, MROWS / 128), 256, GSMEM>>>(qkv_b, nullptr);

    // 2) tensor-core flash attention (split bf16), writes split output
    cudaFuncSetAttribute(attn_mma,
                         cudaFuncAttributeMaxDynamicSharedMemorySize, AT_SMEM);
    attn_mma<<<dim3(SEQ / 128, BATCH * HEADS), 256, AT_SMEM>>>();

    // 3) output projection (WMMA split bf16)
    cudaFuncSetAttribute(gemm_wmma<2>,
                         cudaFuncAttributeMaxDynamicSharedMemorySize, GSMEM);
    gemm_wmma<2><<<dim3(EMB / 128, MROWS / 128), 256, GSMEM>>>(proj_b, out);
}

// round 14
// speedup vs baseline: 1.2254x; 1.1546x over previous
#include <cuda_runtime.h>
#include <cuda_bf16.h>
#include <math.h>
#include <stdint.h>

// Problem constants
#define BATCH 4
#define SEQ   2048
#define EMB   1024
#define HEADS 16
#define HD    64
#define MROWS (BATCH * SEQ)          // 8192
#define QKVN  (3 * EMB)              // 3072

// ---------------------------------------------------------------------------
// Device-global scratch
// ---------------------------------------------------------------------------
__device__ __nv_bfloat16 g_ah[MROWS * EMB], g_al[MROWS * EMB];   // hidden
__device__ __nv_bfloat16 g_wh[QKVN * EMB],  g_wl[QKVN * EMB];    // qkv_w
__device__ __nv_bfloat16 g_ph[EMB * EMB],   g_pl[EMB * EMB];     // proj_w
__device__ __nv_bfloat16 g_aoh[MROWS * EMB], g_aol[MROWS * EMB]; // attn out

__device__ __nv_bfloat16 g_qh[BATCH * HEADS * SEQ * HD], g_ql[BATCH * HEADS * SEQ * HD];
__device__ __nv_bfloat16 g_kh[BATCH * HEADS * SEQ * HD], g_kl[BATCH * HEADS * SEQ * HD];
__device__ __nv_bfloat16 g_vth[BATCH * HEADS * HD * SEQ], g_vtl[BATCH * HEADS * HD * SEQ];

__device__ float g_cos[SEQ * 32], g_sin[SEQ * 32];

// ---------------------------------------------------------------------------
// helpers
// ---------------------------------------------------------------------------
__device__ __forceinline__ uint32_t smem_u32(const void* p) {
    uint32_t a;
    asm("{ .reg .u64 t; cvta.to.shared.u64 t, %1; cvt.u32.u64 %0, t; }"
        : "=r"(a) : "l"(p));
    return a;
}
__device__ __forceinline__ void cp_async16(uint32_t dst, const void* src) {
    asm volatile("cp.async.cg.shared.global [%0], [%1], 16;"
                 :: "r"(dst), "l"(src) : "memory");
}
__device__ __forceinline__ void cp_commit() {
    asm volatile("cp.async.commit_group;" ::: "memory");
}
template <int N>
__device__ __forceinline__ void cp_wait() {
    asm volatile("cp.async.wait_group %0;" :: "n"(N) : "memory");
}
__device__ __forceinline__ void ldsm4(uint32_t* r, uint32_t addr) {
    asm volatile("ldmatrix.sync.aligned.m8n8.x4.shared.b16 {%0,%1,%2,%3}, [%4];"
        : "=r"(r[0]), "=r"(r[1]), "=r"(r[2]), "=r"(r[3]) : "r"(addr));
}
__device__ __forceinline__ void mma16816(float* d, const uint32_t* a,
                                         uint32_t b0, uint32_t b1) {
    asm volatile(
        "mma.sync.aligned.m16n8k16.row.col.f32.bf16.bf16.f32 "
        "{%0,%1,%2,%3}, {%4,%5,%6,%7}, {%8,%9}, {%0,%1,%2,%3};"
        : "+f"(d[0]), "+f"(d[1]), "+f"(d[2]), "+f"(d[3])
        : "r"(a[0]), "r"(a[1]), "r"(a[2]), "r"(a[3]), "r"(b0), "r"(b1));
}
__device__ __forceinline__ uint32_t pack_bf16x2(float lo, float hi) {
    uint32_t r;
    asm("cvt.rn.bf16x2.f32 %0, %1, %2;" : "=r"(r) : "f"(hi), "f"(lo));
    return r;
}
__device__ __forceinline__ float bres(float f) {
    return f - __bfloat162float(__float2bfloat16_rn(f));
}

// ---------------------------------------------------------------------------
// RoPE cos/sin table
// ---------------------------------------------------------------------------
__global__ __launch_bounds__(256)
void costab_kernel()
{
    const int i = blockIdx.x * 256 + threadIdx.x;
    if (i >= SEQ * 32) return;
    const int s = i >> 5, j = i & 31;
    const float invf = powf(10000.0f, -(float)(2 * j) / 64.0f);
    float c, sn;
    sincosf((float)s * invf, &sn, &c);
    g_cos[i] = c;
    g_sin[i] = sn;
}

// ---------------------------------------------------------------------------
// fp32 -> (bf16 hi, bf16 lo) split conversion
// ---------------------------------------------------------------------------
template <int WHICH>
__global__ __launch_bounds__(256)
void split_kernel(const float* __restrict__ x, int n4)
{
    __nv_bfloat16* hi = (WHICH == 0) ? g_ah : (WHICH == 1) ? g_wh : g_ph;
    __nv_bfloat16* lo = (WHICH == 0) ? g_al : (WHICH == 1) ? g_wl : g_pl;
    int i = blockIdx.x * 256 + threadIdx.x;
    if (i >= n4) return;
    float4 v = reinterpret_cast<const float4*>(x)[i];
    __nv_bfloat16 h0 = __float2bfloat16_rn(v.x);
    __nv_bfloat16 h1 = __float2bfloat16_rn(v.y);
    __nv_bfloat16 h2 = __float2bfloat16_rn(v.z);
    __nv_bfloat16 h3 = __float2bfloat16_rn(v.w);
    __nv_bfloat16 l0 = __float2bfloat16_rn(v.x - __bfloat162float(h0));
    __nv_bfloat16 l1 = __float2bfloat16_rn(v.y - __bfloat162float(h1));
    __nv_bfloat16 l2 = __float2bfloat16_rn(v.z - __bfloat162float(h2));
    __nv_bfloat16 l3 = __float2bfloat16_rn(v.w - __bfloat162float(h3));
    __nv_bfloat162* hp = reinterpret_cast<__nv_bfloat162*>(hi) + 2 * i;
    __nv_bfloat162* lp = reinterpret_cast<__nv_bfloat162*>(lo) + 2 * i;
    hp[0] = __halves2bfloat162(h0, h1);
    hp[1] = __halves2bfloat162(h2, h3);
    lp[0] = __halves2bfloat162(l0, l1);
    lp[1] = __halves2bfloat162(l2, l3);
}

// ---------------------------------------------------------------------------
// Raw-mma split-bf16 GEMM. CTA 128x128, BK=32, 3-stage cp.async, 8 warps 32x64.
// Swizzled smem: row = 64B (4 x 16B chunks), chunk c stored at c ^ ((row>>1)&3).
// All ldmatrix addresses 16B-aligned and phase-conflict-free.
// MODE 1: fused RoPE/split/V-transpose epilogue.  MODE 2: plain C + bias.
// ---------------------------------------------------------------------------
#define BK       32
#define ROW_B    64                        // bytes per row (32 bf16)
#define TILE_B   (128 * ROW_B)             // 8192 bytes per tile
#define STAGE_B  (4 * TILE_B)              // Ah, Al, Bh, Bl = 32768
#define NSTAGE   3
#define GSMEM    (NSTAGE * STAGE_B)        // 98304
#define EPI_LD   132

__device__ __forceinline__ uint32_t swz_off(int row, int chunk) {
    return (uint32_t)(row * ROW_B + ((chunk ^ ((row >> 1) & 3)) << 4));
}

__device__ __forceinline__ void cp_chunk(
    uint32_t sbuf, int c, int tid,
    const __nv_bfloat16* Ah, const __nv_bfloat16* Al,
    const __nv_bfloat16* Bh, const __nv_bfloat16* Bl,
    int m0, int n0)
{
    const int k0 = c * BK;
    const __nv_bfloat16* srcs[4] = {Ah, Al, Bh, Bl};
#pragma unroll
    for (int t = 0; t < 4; t++) {
        const int row0 = (t < 2) ? m0 : n0;
        const __nv_bfloat16* src = srcs[t];
#pragma unroll
        for (int i = 0; i < 2; i++) {
            const int idx = tid + i * 256;       // 0..511
            const int r   = idx >> 2;            // 0..127
            const int seg = idx & 3;             // 16B chunk
            cp_async16(sbuf + t * TILE_B + swz_off(r, seg),
                       src + (size_t)(row0 + r) * EMB + k0 + seg * 8);
        }
    }
}

template <int MODE>
__global__ __launch_bounds__(256, 2)
void gemm_mma(const float* __restrict__ bias, float* __restrict__ C)
{
    extern __shared__ __align__(16) char smem[];
    const int tid  = threadIdx.x;
    const int wid  = tid >> 5;
    const int lane = tid & 31;
    const int gid  = lane >> 2;
    const int tidg = lane & 3;
    const int m0 = blockIdx.y * 128;
    const int n0 = blockIdx.x * 128;

    const __nv_bfloat16* Ah = (MODE == 1) ? g_ah : g_aoh;
    const __nv_bfloat16* Al = (MODE == 1) ? g_al : g_aol;
    const __nv_bfloat16* Bh = (MODE == 1) ? g_wh : g_ph;
    const __nv_bfloat16* Bl = (MODE == 1) ? g_wl : g_pl;

    const int warp_m = (wid & 3) * 32;
    const int warp_n = (wid >> 2) * 64;

    // ldmatrix lane address components
    // A: row = warp_m + mt*16 + (lane&15); chunk = ks/8 + (lane>>4)
    const int arow_b = warp_m + (lane & 15);
    const int acsel  = lane >> 4;           // 0 or 1
    // B: row = warp_n + np*16 + (lane&7) + 8*(lane>>4); chunk = ks/8 + ((lane>>3)&1)
    const int brow_b = warp_n + (lane & 7) + 8 * (lane >> 4);
    const int bcsel  = (lane >> 3) & 1;

    float acc[2][8][4];
#pragma unroll
    for (int mt = 0; mt < 2; mt++)
#pragma unroll
        for (int nn = 0; nn < 8; nn++)
#pragma unroll
            for (int j = 0; j < 4; j++) acc[mt][nn][j] = 0.0f;

    const uint32_t sb = smem_u32(smem);
    cp_chunk(sb, 0, tid, Ah, Al, Bh, Bl, m0, n0);
    cp_commit();
    cp_chunk(sb + STAGE_B, 1, tid, Ah, Al, Bh, Bl, m0, n0);
    cp_commit();

    const int NCH = EMB / BK;   // 32
    int stage = 0;
    for (int c = 0; c < NCH; c++) {
        if (c + 2 < NCH) {
            int ps = stage + 2; if (ps >= NSTAGE) ps -= NSTAGE;
            cp_chunk(sb + ps * STAGE_B, c + 2, tid, Ah, Al, Bh, Bl, m0, n0);
            cp_commit();
            cp_wait<2>();
        } else if (c + 1 < NCH) {
            cp_wait<1>();
        } else {
            cp_wait<0>();
        }
        __syncthreads();

        const uint32_t abase = sb + stage * STAGE_B;
        const uint32_t bbase = abase + 2 * TILE_B;

#pragma unroll
        for (int ks2 = 0; ks2 < 2; ks2++) {      // ks = 16*ks2
            const int ccA = 2 * ks2 + acsel;
            const int ccB = 2 * ks2 + bcsel;

            uint32_t ah[2][4], al[2][4];
#pragma unroll
            for (int mt = 0; mt < 2; mt++) {
                const uint32_t ao = swz_off(arow_b + mt * 16, ccA);
                ldsm4(ah[mt], abase + ao);
                ldsm4(al[mt], abase + TILE_B + ao);
            }

#pragma unroll
            for (int g = 0; g < 2; g++) {        // np = 2g, 2g+1
                uint32_t bh[2][4], bl[2][4];
#pragma unroll
                for (int np2 = 0; np2 < 2; np2++) {
                    const uint32_t bo = swz_off(brow_b + (2 * g + np2) * 16, ccB);
                    ldsm4(bh[np2], bbase + bo);
                    ldsm4(bl[np2], bbase + TILE_B + bo);
                }
                // term-major: dependent MMAs on one acc are 8 apart
#pragma unroll
                for (int t3 = 0; t3 < 3; t3++) {
                    const uint32_t (*Af)[4] = (t3 == 2) ? al : ah;
                    const uint32_t (*Bf)[4] = (t3 == 1) ? bl : bh;
#pragma unroll
                    for (int np2 = 0; np2 < 2; np2++)
#pragma unroll
                        for (int mt = 0; mt < 2; mt++) {
                            const int nn = (2 * g + np2) * 2;
                            mma16816(acc[mt][nn],     Af[mt], Bf[np2][0], Bf[np2][1]);
                            mma16816(acc[mt][nn + 1], Af[mt], Bf[np2][2], Bf[np2][3]);
                        }
                }
            }
        }
        __syncthreads();
        if (++stage == NSTAGE) stage = 0;
    }

    // Stage fp32 accumulators in smem
    float* es = reinterpret_cast<float*>(smem);
#pragma unroll
    for (int mt = 0; mt < 2; mt++)
#pragma unroll
        for (int nn = 0; nn < 8; nn++) {
            const int col = warp_n + nn * 8 + 2 * tidg;
            const int r0  = warp_m + mt * 16 + gid;
            *reinterpret_cast<float2*>(&es[r0 * EPI_LD + col]) =
                make_float2(acc[mt][nn][0], acc[mt][nn][1]);
            *reinterpret_cast<float2*>(&es[(r0 + 8) * EPI_LD + col]) =
                make_float2(acc[mt][nn][2], acc[mt][nn][3]);
        }
    __syncthreads();

    if (MODE == 2) {
#pragma unroll
        for (int i = 0; i < 16; i++) {
            const int idx  = tid + i * 256;
            const int row  = idx >> 5;
            const int col4 = idx & 31;
            const int m = m0 + row;
            const int n = n0 + col4 * 4;
            const float4 bv = *reinterpret_cast<const float4*>(bias + n);
            float4 v;
            v.x = es[row * EPI_LD + col4 * 4 + 0] + bv.x;
            v.y = es[row * EPI_LD + col4 * 4 + 1] + bv.y;
            v.z = es[row * EPI_LD + col4 * 4 + 2] + bv.z;
            v.w = es[row * EPI_LD + col4 * 4 + 3] + bv.w;
            *reinterpret_cast<float4*>(&C[(size_t)m * EMB + n]) = v;
        }
        return;
    }

    // ---- MODE 1 fused epilogue ----
    const int part = n0 >> 10;           // 0=q 1=k 2=v
    if (part < 2) {
        __nv_bfloat16* dh = part ? g_kh : g_qh;
        __nv_bfloat16* dl = part ? g_kl : g_ql;
        const float qscale = part ? 1.0f : 0.125f;
#pragma unroll
        for (int i = 0; i < 16; i++) {
            const int idx  = tid + i * 256;
            const int row  = idx >> 5;
            const int col4 = idx & 31;
            const int cc   = col4 * 4;
            const int n    = n0 + cc;
            const int m    = m0 + row;
            const int h    = (n & 1023) >> 6;
            const int d    = n & 63;
            const int b    = m >> 11, s = m & 2047;
            const int dp   = d & 31;

            const float4 bv  = *reinterpret_cast<const float4*>(bias + n);
            const float4 bvp = *reinterpret_cast<const float4*>(bias + (n ^ 32));
            const float4 cv  = *reinterpret_cast<const float4*>(g_cos + s * 32 + dp);
            const float4 sv  = *reinterpret_cast<const float4*>(g_sin + s * 32 + dp);
            const float bvx[4]  = {bv.x, bv.y, bv.z, bv.w};
            const float bvpx[4] = {bvp.x, bvp.y, bvp.z, bvp.w};
            const float cvx[4]  = {cv.x, cv.y, cv.z, cv.w};
            const float svx[4]  = {sv.x, sv.y, sv.z, sv.w};

            const float sgn = (d < 32) ? -1.0f : 1.0f;
            uint32_t hw[2], lw[2];
#pragma unroll
            for (int p2 = 0; p2 < 2; p2++) {
                float f[2];
#pragma unroll
                for (int q2 = 0; q2 < 2; q2++) {
                    const int j2 = p2 * 2 + q2;
                    const float x  = es[row * EPI_LD + cc + j2] + bvx[j2];
                    const float xp = es[row * EPI_LD + ((cc + j2) ^ 32)] + bvpx[j2];
                    f[q2] = (x * cvx[j2] + sgn * xp * svx[j2]) * qscale;
                }
                hw[p2] = pack_bf16x2(f[0], f[1]);
                lw[p2] = pack_bf16x2(bres(f[0]), bres(f[1]));
            }
            const size_t base = ((size_t)(b * HEADS + h) * SEQ + s) * HD + d;
            *reinterpret_cast<uint2*>(dh + base) = make_uint2(hw[0], hw[1]);
            *reinterpret_cast<uint2*>(dl + base) = make_uint2(lw[0], lw[1]);
        }
    } else {
        const int dloc = tid & 127;
        const int half = tid >> 7;
        const int h    = ((n0 & 1023) >> 6) + (dloc >> 6);
        const int d    = dloc & 63;
        const int b    = m0 >> 11;
        const int sbase = (m0 & 2047) + half * 64;
        const float bvv = bias[n0 + dloc];
        const size_t vb = ((size_t)(b * HEADS + h) * HD + d) * SEQ + sbase;
#pragma unroll
        for (int jj = 0; jj < 8; jj++) {
            uint32_t hw[4], lw[4];
#pragma unroll
            for (int j2 = 0; j2 < 4; j2++) {
                const float f0 = es[(half * 64 + jj * 8 + 2 * j2)     * EPI_LD + dloc] + bvv;
                const float f1 = es[(half * 64 + jj * 8 + 2 * j2 + 1) * EPI_LD + dloc] + bvv;
                hw[j2] = pack_bf16x2(f0, f1);
                lw[j2] = pack_bf16x2(bres(f0), bres(f1));
            }
            *reinterpret_cast<uint4*>(g_vth + vb + jj * 8) =
                make_uint4(hw[0], hw[1], hw[2], hw[3]);
            *reinterpret_cast<uint4*>(g_vtl + vb + jj * 8) =
                make_uint4(lw[0], lw[1], lw[2], lw[3]);
        }
    }
}

// ---------------------------------------------------------------------------
// Tensor-core flash attention (unchanged). grid=(SEQ/128, B*H).
// ---------------------------------------------------------------------------
#define AK_STR   72
#define ATILE_EL (64 * AK_STR)
#define ABUF_EL  (4 * ATILE_EL)
#define AT_SMEM  (2 * ABUF_EL * 2)      // 73728 bytes

__device__ __forceinline__ void attn_stage(uint32_t sb, int buf, int kb,
                                           size_t hbase, size_t vbase, int tid)
{
#pragma unroll
    for (int i = 0; i < 8; i++) {
        const int t  = i >> 1;
        const int r  = (tid >> 3) + 32 * (i & 1);
        const int ch = tid & 7;
        const __nv_bfloat16* src;
        if (t == 0)      src = g_kh  + hbase + (size_t)(kb * 64 + r) * HD + ch * 8;
        else if (t == 1) src = g_kl  + hbase + (size_t)(kb * 64 + r) * HD + ch * 8;
        else if (t == 2) src = g_vth + vbase + (size_t)r * SEQ + kb * 64 + ch * 8;
        else             src = g_vtl + vbase + (size_t)r * SEQ + kb * 64 + ch * 8;
        cp_async16(sb + (buf * ABUF_EL + t * ATILE_EL + r * AK_STR + ch * 8) * 2, src);
    }
}

__global__ __launch_bounds__(256)
void attn_mma()
{
    extern __shared__ __align__(16) __nv_bfloat16 sk[];
    const uint32_t sb = smem_u32(sk);
    const int tid  = threadIdx.x;
    const int wid  = tid >> 5;
    const int lane = tid & 31;
    const int gid  = lane >> 2;
    const int tidg = lane & 3;
    const int qb   = blockIdx.x;
    const int head = blockIdx.y;

    const size_t hbase = (size_t)head * SEQ * HD;
    const size_t vbase = (size_t)head * HD * SEQ;

    uint32_t qah[4][4], qal[4][4];
    {
        const int r0 = qb * 128 + wid * 16 + gid;
        const uint32_t* q0h = reinterpret_cast<const uint32_t*>(g_qh + hbase + (size_t)r0 * HD);
        const uint32_t* q1h = reinterpret_cast<const uint32_t*>(g_qh + hbase + (size_t)(r0 + 8) * HD);
        const uint32_t* q0l = reinterpret_cast<const uint32_t*>(g_ql + hbase + (size_t)r0 * HD);
        const uint32_t* q1l = reinterpret_cast<const uint32_t*>(g_ql + hbase + (size_t)(r0 + 8) * HD);
#pragma unroll
        for (int ks = 0; ks < 4; ks++) {
            qah[ks][0] = q0h[ks * 8 + tidg];
            qah[ks][1] = q1h[ks * 8 + tidg];
            qah[ks][2] = q0h[ks * 8 + tidg + 4];
            qah[ks][3] = q1h[ks * 8 + tidg + 4];
            qal[ks][0] = q0l[ks * 8 + tidg];
            qal[ks][1] = q1l[ks * 8 + tidg];
            qal[ks][2] = q0l[ks * 8 + tidg + 4];
            qal[ks][3] = q1l[ks * 8 + tidg + 4];
        }
    }

    float o[8][4];
#pragma unroll
    for (int nt = 0; nt < 8; nt++)
#pragma unroll
        for (int j = 0; j < 4; j++) o[nt][j] = 0.0f;
    float m0 = -1e30f, m1 = -1e30f, l0 = 0.0f, l1 = 0.0f;

    attn_stage(sb, 0, 0, hbase, vbase, tid);
    cp_commit();

    const int NKB = SEQ / 64;
    for (int kb = 0; kb < NKB; kb++) {
        if (kb + 1 < NKB) {
            attn_stage(sb, (kb + 1) & 1, kb + 1, hbase, vbase, tid);
            cp_commit();
            cp_wait<1>();
        } else {
            cp_wait<0>();
        }
        __syncthreads();

        const __nv_bfloat16* bs = sk + (kb & 1) * ABUF_EL;
        const __nv_bfloat16* Kh = bs;
        const __nv_bfloat16* Kl = bs + ATILE_EL;
        const __nv_bfloat16* Vh = bs + 2 * ATILE_EL;
        const __nv_bfloat16* Vl = bs + 3 * ATILE_EL;

        float s[8][4];
#pragma unroll
        for (int nt = 0; nt < 8; nt++)
#pragma unroll
            for (int j = 0; j < 4; j++) s[nt][j] = 0.0f;

#pragma unroll
        for (int ks = 0; ks < 4; ks++) {
#pragma unroll
            for (int nt = 0; nt < 8; nt++) {
                const uint32_t* krh = reinterpret_cast<const uint32_t*>(
                    Kh + (nt * 8 + gid) * AK_STR);
                const uint32_t* krl = reinterpret_cast<const uint32_t*>(
                    Kl + (nt * 8 + gid) * AK_STR);
                const uint32_t bh0 = krh[8 * ks + tidg];
                const uint32_t bh1 = krh[8 * ks + tidg + 4];
                const uint32_t bl0 = krl[8 * ks + tidg];
                const uint32_t bl1 = krl[8 * ks + tidg + 4];
                mma16816(s[nt], qah[ks], bh0, bh1);
                mma16816(s[nt], qah[ks], bl0, bl1);
                mma16816(s[nt], qal[ks], bh0, bh1);
            }
        }

        float mx0 = -1e30f, mx1 = -1e30f;
#pragma unroll
        for (int nt = 0; nt < 8; nt++) {
            mx0 = fmaxf(mx0, fmaxf(s[nt][0], s[nt][1]));
            mx1 = fmaxf(mx1, fmaxf(s[nt][2], s[nt][3]));
        }
        mx0 = fmaxf(mx0, __shfl_xor_sync(0xffffffffu, mx0, 1));
        mx0 = fmaxf(mx0, __shfl_xor_sync(0xffffffffu, mx0, 2));
        mx1 = fmaxf(mx1, __shfl_xor_sync(0xffffffffu, mx1, 1));
        mx1 = fmaxf(mx1, __shfl_xor_sync(0xffffffffu, mx1, 2));
        const float mn0 = fmaxf(m0, mx0), mn1 = fmaxf(m1, mx1);
        const float c0 = __expf(m0 - mn0), c1 = __expf(m1 - mn1);
        float rs0 = 0.0f, rs1 = 0.0f;
#pragma unroll
        for (int nt = 0; nt < 8; nt++) {
            s[nt][0] = __expf(s[nt][0] - mn0);
            s[nt][1] = __expf(s[nt][1] - mn0);
            s[nt][2] = __expf(s[nt][2] - mn1);
            s[nt][3] = __expf(s[nt][3] - mn1);
            rs0 += s[nt][0] + s[nt][1];
            rs1 += s[nt][2] + s[nt][3];
        }
        rs0 += __shfl_xor_sync(0xffffffffu, rs0, 1);
        rs0 += __shfl_xor_sync(0xffffffffu, rs0, 2);
        rs1 += __shfl_xor_sync(0xffffffffu, rs1, 1);
        rs1 += __shfl_xor_sync(0xffffffffu, rs1, 2);
        l0 = l0 * c0 + rs0;  l1 = l1 * c1 + rs1;
        m0 = mn0;  m1 = mn1;
#pragma unroll
        for (int nt = 0; nt < 8; nt++) {
            o[nt][0] *= c0; o[nt][1] *= c0;
            o[nt][2] *= c1; o[nt][3] *= c1;
        }

#pragma unroll
        for (int ks = 0; ks < 4; ks++) {
            uint32_t pah[4], pal[4];
            pah[0] = pack_bf16x2(s[2 * ks][0], s[2 * ks][1]);
            pah[1] = pack_bf16x2(s[2 * ks][2], s[2 * ks][3]);
            pah[2] = pack_bf16x2(s[2 * ks + 1][0], s[2 * ks + 1][1]);
            pah[3] = pack_bf16x2(s[2 * ks + 1][2], s[2 * ks + 1][3]);
            pal[0] = pack_bf16x2(bres(s[2 * ks][0]), bres(s[2 * ks][1]));
            pal[1] = pack_bf16x2(bres(s[2 * ks][2]), bres(s[2 * ks][3]));
            pal[2] = pack_bf16x2(bres(s[2 * ks + 1][0]), bres(s[2 * ks + 1][1]));
            pal[3] = pack_bf16x2(bres(s[2 * ks + 1][2]), bres(s[2 * ks + 1][3]));
#pragma unroll
            for (int nt = 0; nt < 8; nt++) {
                const uint32_t* vrh = reinterpret_cast<const uint32_t*>(
                    Vh + (nt * 8 + gid) * AK_STR);
                const uint32_t* vrl = reinterpret_cast<const uint32_t*>(
                    Vl + (nt * 8 + gid) * AK_STR);
                const uint32_t bh0 = vrh[8 * ks + tidg];
                const uint32_t bh1 = vrh[8 * ks + tidg + 4];
                const uint32_t bl0 = vrl[8 * ks + tidg];
                const uint32_t bl1 = vrl[8 * ks + tidg + 4];
                mma16816(o[nt], pah, bh0, bh1);
                mma16816(o[nt], pah, bl0, bl1);
                mma16816(o[nt], pal, bh0, bh1);
            }
        }
        __syncthreads();
    }

    const float i0 = 1.0f / l0, i1 = 1.0f / l1;
    const int b = head >> 4, h = head & 15;
    const int s0 = qb * 128 + wid * 16;
#pragma unroll
    for (int nt = 0; nt < 8; nt++) {
        const float f0 = o[nt][0] * i0, f1 = o[nt][1] * i0;
        const float f2 = o[nt][2] * i1, f3 = o[nt][3] * i1;
        const size_t base0 = (size_t)(b * SEQ + s0 + gid) * EMB +
                             h * 64 + nt * 8 + 2 * tidg;
        const size_t base1 = (size_t)(b * SEQ + s0 + gid + 8) * EMB +
                             h * 64 + nt * 8 + 2 * tidg;
        *reinterpret_cast<uint32_t*>(g_aoh + base0) = pack_bf16x2(f0, f1);
        *reinterpret_cast<uint32_t*>(g_aol + base0) = pack_bf16x2(bres(f0), bres(f1));
        *reinterpret_cast<uint32_t*>(g_aoh + base1) = pack_bf16x2(f2, f3);
        *reinterpret_cast<uint32_t*>(g_aol + base1) = pack_bf16x2(bres(f2), bres(f3));
    }
}

// ---------------------------------------------------------------------------
extern "C" void kernel_launch(void* const* d_in, const int* in_sizes, int n_in,
                              void* d_out, int out_size)
{
    const float* hidden = (const float*)d_in[0];
    const float* qkv_w  = (const float*)d_in[1];
    const float* qkv_b  = (const float*)d_in[2];
    const float* proj_w = (const float*)d_in[3];
    const float* proj_b = (const float*)d_in[4];
    float* out = (float*)d_out;

    // 0) cos/sin table + splits fp32 -> bf16 hi/lo
    costab_kernel<<<(SEQ * 32 + 255) / 256, 256>>>();
    split_kernel<0><<<(MROWS * EMB / 4 + 255) / 256, 256>>>(hidden, MROWS * EMB / 4);
    split_kernel<1><<<(QKVN * EMB / 4 + 255) / 256, 256>>>(qkv_w, QKVN * EMB / 4);
    split_kernel<2><<<(EMB * EMB / 4 + 255) / 256, 256>>>(proj_w, EMB * EMB / 4);

    // 1) QKV GEMM (raw-mma, swizzled smem, 3-stage) + fused RoPE/split/V-T epi
    cudaFuncSetAttribute(gemm_mma<1>,
                         cudaFuncAttributeMaxDynamicSharedMemorySize, GSMEM);
    gemm_mma<1><<<dim3(QKVN / 128, MROWS / 128), 256, GSMEM>>>(qkv_b, nullptr);

    // 2) tensor-core flash attention (split bf16)
    cudaFuncSetAttribute(attn_mma,
                         cudaFuncAttributeMaxDynamicSharedMemorySize, AT_SMEM);
    attn_mma<<<dim3(SEQ / 128, BATCH * HEADS), 256, AT_SMEM>>>();

    // 3) output projection
    cudaFuncSetAttribute(gemm_mma<2>,
                         cudaFuncAttributeMaxDynamicSharedMemorySize, GSMEM);
    gemm_mma<2><<<dim3(EMB / 128, MROWS / 128), 256, GSMEM>>>(proj_b, out);
}

// round 15
// speedup vs baseline: 2.8056x; 2.2895x over previous
#include <cuda_runtime.h>
#include <cuda_fp16.h>
#include <math.h>
#include <stdint.h>

// Problem constants
#define BATCH 4
#define SEQ   2048
#define EMB   1024
#define HEADS 16
#define HD    64
#define MROWS (BATCH * SEQ)          // 8192
#define QKVN  (3 * EMB)              // 3072

// ---------------------------------------------------------------------------
// Device-global scratch (fp16 single precision operands)
// ---------------------------------------------------------------------------
__device__ __half g_ah[MROWS * EMB];      // hidden
__device__ __half g_wh[QKVN * EMB];       // qkv_w
__device__ __half g_ph[EMB * EMB];        // proj_w
__device__ __half g_aoh[MROWS * EMB];     // attn out

__device__ __half g_qh[BATCH * HEADS * SEQ * HD];
__device__ __half g_kh[BATCH * HEADS * SEQ * HD];
__device__ __half g_vth[BATCH * HEADS * HD * SEQ];   // [B,H,hd,S]

__device__ float g_cos[SEQ * 32], g_sin[SEQ * 32];

// ---------------------------------------------------------------------------
// helpers
// ---------------------------------------------------------------------------
__device__ __forceinline__ uint32_t smem_u32(const void* p) {
    uint32_t a;
    asm("{ .reg .u64 t; cvta.to.shared.u64 t, %1; cvt.u32.u64 %0, t; }"
        : "=r"(a) : "l"(p));
    return a;
}
__device__ __forceinline__ void cp_async16(uint32_t dst, const void* src) {
    asm volatile("cp.async.cg.shared.global [%0], [%1], 16;"
                 :: "r"(dst), "l"(src) : "memory");
}
__device__ __forceinline__ void cp_commit() {
    asm volatile("cp.async.commit_group;" ::: "memory");
}
template <int N>
__device__ __forceinline__ void cp_wait() {
    asm volatile("cp.async.wait_group %0;" :: "n"(N) : "memory");
}
__device__ __forceinline__ void ldsm4(uint32_t* r, uint32_t addr) {
    asm volatile("ldmatrix.sync.aligned.m8n8.x4.shared.b16 {%0,%1,%2,%3}, [%4];"
        : "=r"(r[0]), "=r"(r[1]), "=r"(r[2]), "=r"(r[3]) : "r"(addr));
}
// D += A*B, m16n8k16 row.col fp16 -> f32
__device__ __forceinline__ void mma16816(float* d, const uint32_t* a,
                                         uint32_t b0, uint32_t b1) {
    asm volatile(
        "mma.sync.aligned.m16n8k16.row.col.f32.f16.f16.f32 "
        "{%0,%1,%2,%3}, {%4,%5,%6,%7}, {%8,%9}, {%0,%1,%2,%3};"
        : "+f"(d[0]), "+f"(d[1]), "+f"(d[2]), "+f"(d[3])
        : "r"(a[0]), "r"(a[1]), "r"(a[2]), "r"(a[3]), "r"(b0), "r"(b1));
}
// pack two f32 into f16x2 (first arg in low half)
__device__ __forceinline__ uint32_t pack_f16x2(float lo, float hi) {
    uint32_t r;
    asm("cvt.rn.f16x2.f32 %0, %1, %2;" : "=r"(r) : "f"(hi), "f"(lo));
    return r;
}

// ---------------------------------------------------------------------------
// RoPE cos/sin table
// ---------------------------------------------------------------------------
__global__ __launch_bounds__(256)
void costab_kernel()
{
    const int i = blockIdx.x * 256 + threadIdx.x;
    if (i >= SEQ * 32) return;
    const int s = i >> 5, j = i & 31;
    const float invf = powf(10000.0f, -(float)(2 * j) / 64.0f);
    float c, sn;
    sincosf((float)s * invf, &sn, &c);
    g_cos[i] = c;
    g_sin[i] = sn;
}

// ---------------------------------------------------------------------------
// fp32 -> fp16 conversion.  WHICH: 0=hidden 1=qkv_w 2=proj_w
// ---------------------------------------------------------------------------
template <int WHICH>
__global__ __launch_bounds__(256)
void split_kernel(const float* __restrict__ x, int n4)
{
    __half* hi = (WHICH == 0) ? g_ah : (WHICH == 1) ? g_wh : g_ph;
    int i = blockIdx.x * 256 + threadIdx.x;
    if (i >= n4) return;
    float4 v = reinterpret_cast<const float4*>(x)[i];
    uint2 o;
    o.x = pack_f16x2(v.x, v.y);
    o.y = pack_f16x2(v.z, v.w);
    *(reinterpret_cast<uint2*>(hi) + i) = o;
}

// ---------------------------------------------------------------------------
// Raw-mma fp16 GEMM. CTA 128x128, BK=32, 4-stage cp.async, 8 warps 32x64.
// Swizzled smem: row = 64B (4 x 16B chunks), chunk c at c ^ ((row>>1)&3).
// MODE 1: fused RoPE + V-transpose epilogue.  MODE 2: plain C + bias.
// ---------------------------------------------------------------------------
#define BK       32
#define ROW_B    64                        // bytes per row (32 fp16)
#define TILE_B   (128 * ROW_B)             // 8192 bytes per tile
#define STAGE_B  (2 * TILE_B)              // A, B = 16384
#define NSTAGE   4
#define GSMEM    69632                     // max(4*16384, 128*132*4=67584)
#define EPI_LD   132

__device__ __forceinline__ uint32_t swz_off(int row, int chunk) {
    return (uint32_t)(row * ROW_B + ((chunk ^ ((row >> 1) & 3)) << 4));
}

__device__ __forceinline__ void cp_chunk(
    uint32_t sbuf, int c, int tid,
    const __half* A, const __half* B, int m0, int n0)
{
    const int k0 = c * BK;
#pragma unroll
    for (int t = 0; t < 2; t++) {
        const int row0 = (t == 0) ? m0 : n0;
        const __half* src = (t == 0) ? A : B;
#pragma unroll
        for (int i = 0; i < 2; i++) {
            const int idx = tid + i * 256;       // 0..511
            const int r   = idx >> 2;            // 0..127
            const int seg = idx & 3;             // 16B chunk
            cp_async16(sbuf + t * TILE_B + swz_off(r, seg),
                       src + (size_t)(row0 + r) * EMB + k0 + seg * 8);
        }
    }
}

template <int MODE>
__global__ __launch_bounds__(256, 2)
void gemm_mma(const float* __restrict__ bias, float* __restrict__ C)
{
    extern __shared__ __align__(16) char smem[];
    const int tid  = threadIdx.x;
    const int wid  = tid >> 5;
    const int lane = tid & 31;
    const int gid  = lane >> 2;
    const int tidg = lane & 3;
    const int m0 = blockIdx.y * 128;
    const int n0 = blockIdx.x * 128;

    const __half* A = (MODE == 1) ? g_ah : g_aoh;
    const __half* B = (MODE == 1) ? g_wh : g_ph;

    const int warp_m = (wid & 3) * 32;
    const int warp_n = (wid >> 2) * 64;

    const int arow_b = warp_m + (lane & 15);
    const int acsel  = lane >> 4;
    const int brow_b = warp_n + (lane & 7) + 8 * (lane >> 4);
    const int bcsel  = (lane >> 3) & 1;

    float acc[2][8][4];
#pragma unroll
    for (int mt = 0; mt < 2; mt++)
#pragma unroll
        for (int nn = 0; nn < 8; nn++)
#pragma unroll
            for (int j = 0; j < 4; j++) acc[mt][nn][j] = 0.0f;

    const uint32_t sb = smem_u32(smem);
    cp_chunk(sb,               0, tid, A, B, m0, n0); cp_commit();
    cp_chunk(sb + STAGE_B,     1, tid, A, B, m0, n0); cp_commit();
    cp_chunk(sb + 2 * STAGE_B, 2, tid, A, B, m0, n0); cp_commit();

    const int NCH = EMB / BK;   // 32
    int stage = 0;
    for (int c = 0; c < NCH; c++) {
        if (c + 3 < NCH) {
            int ps = stage + 3; if (ps >= NSTAGE) ps -= NSTAGE;
            cp_chunk(sb + ps * STAGE_B, c + 3, tid, A, B, m0, n0);
            cp_commit();
            cp_wait<3>();
        } else if (c + 2 < NCH) {
            cp_wait<2>();
        } else if (c + 1 < NCH) {
            cp_wait<1>();
        } else {
            cp_wait<0>();
        }
        __syncthreads();

        const uint32_t abase = sb + stage * STAGE_B;
        const uint32_t bbase = abase + TILE_B;

#pragma unroll
        for (int ks2 = 0; ks2 < 2; ks2++) {
            const int ccA = 2 * ks2 + acsel;
            const int ccB = 2 * ks2 + bcsel;

            uint32_t ah[2][4];
#pragma unroll
            for (int mt = 0; mt < 2; mt++)
                ldsm4(ah[mt], abase + swz_off(arow_b + mt * 16, ccA));

#pragma unroll
            for (int g = 0; g < 2; g++) {
                uint32_t bh[2][4];
#pragma unroll
                for (int np2 = 0; np2 < 2; np2++)
                    ldsm4(bh[np2], bbase + swz_off(brow_b + (2 * g + np2) * 16, ccB));
#pragma unroll
                for (int np2 = 0; np2 < 2; np2++)
#pragma unroll
                    for (int mt = 0; mt < 2; mt++) {
                        const int nn = (2 * g + np2) * 2;
                        mma16816(acc[mt][nn],     ah[mt], bh[np2][0], bh[np2][1]);
                        mma16816(acc[mt][nn + 1], ah[mt], bh[np2][2], bh[np2][3]);
                    }
            }
        }
        __syncthreads();
        if (++stage == NSTAGE) stage = 0;
    }

    // Stage fp32 accumulators in smem
    float* es = reinterpret_cast<float*>(smem);
#pragma unroll
    for (int mt = 0; mt < 2; mt++)
#pragma unroll
        for (int nn = 0; nn < 8; nn++) {
            const int col = warp_n + nn * 8 + 2 * tidg;
            const int r0  = warp_m + mt * 16 + gid;
            *reinterpret_cast<float2*>(&es[r0 * EPI_LD + col]) =
                make_float2(acc[mt][nn][0], acc[mt][nn][1]);
            *reinterpret_cast<float2*>(&es[(r0 + 8) * EPI_LD + col]) =
                make_float2(acc[mt][nn][2], acc[mt][nn][3]);
        }
    __syncthreads();

    if (MODE == 2) {
#pragma unroll
        for (int i = 0; i < 16; i++) {
            const int idx  = tid + i * 256;
            const int row  = idx >> 5;
            const int col4 = idx & 31;
            const int m = m0 + row;
            const int n = n0 + col4 * 4;
            const float4 bv = *reinterpret_cast<const float4*>(bias + n);
            float4 v;
            v.x = es[row * EPI_LD + col4 * 4 + 0] + bv.x;
            v.y = es[row * EPI_LD + col4 * 4 + 1] + bv.y;
            v.z = es[row * EPI_LD + col4 * 4 + 2] + bv.z;
            v.w = es[row * EPI_LD + col4 * 4 + 3] + bv.w;
            *reinterpret_cast<float4*>(&C[(size_t)m * EMB + n]) = v;
        }
        return;
    }

    // ---- MODE 1 fused epilogue ----
    const int part = n0 >> 10;           // 0=q 1=k 2=v
    if (part < 2) {
        __half* dh = part ? g_kh : g_qh;
        const float qscale = part ? 1.0f : 0.125f;
#pragma unroll
        for (int i = 0; i < 16; i++) {
            const int idx  = tid + i * 256;
            const int row  = idx >> 5;
            const int col4 = idx & 31;
            const int cc   = col4 * 4;
            const int n    = n0 + cc;
            const int m    = m0 + row;
            const int h    = (n & 1023) >> 6;
            const int d    = n & 63;
            const int b    = m >> 11, s = m & 2047;
            const int dp   = d & 31;

            const float4 bv  = *reinterpret_cast<const float4*>(bias + n);
            const float4 bvp = *reinterpret_cast<const float4*>(bias + (n ^ 32));
            const float4 cv  = *reinterpret_cast<const float4*>(g_cos + s * 32 + dp);
            const float4 sv  = *reinterpret_cast<const float4*>(g_sin + s * 32 + dp);
            const float bvx[4]  = {bv.x, bv.y, bv.z, bv.w};
            const float bvpx[4] = {bvp.x, bvp.y, bvp.z, bvp.w};
            const float cvx[4]  = {cv.x, cv.y, cv.z, cv.w};
            const float svx[4]  = {sv.x, sv.y, sv.z, sv.w};

            const float sgn = (d < 32) ? -1.0f : 1.0f;
            uint32_t hw[2];
#pragma unroll
            for (int p2 = 0; p2 < 2; p2++) {
                float f[2];
#pragma unroll
                for (int q2 = 0; q2 < 2; q2++) {
                    const int j2 = p2 * 2 + q2;
                    const float x  = es[row * EPI_LD + cc + j2] + bvx[j2];
                    const float xp = es[row * EPI_LD + ((cc + j2) ^ 32)] + bvpx[j2];
                    f[q2] = (x * cvx[j2] + sgn * xp * svx[j2]) * qscale;
                }
                hw[p2] = pack_f16x2(f[0], f[1]);
            }
            const size_t base = ((size_t)(b * HEADS + h) * SEQ + s) * HD + d;
            *reinterpret_cast<uint2*>(dh + base) = make_uint2(hw[0], hw[1]);
        }
    } else {
        const int dloc = tid & 127;
        const int half2_ = tid >> 7;
        const int h    = ((n0 & 1023) >> 6) + (dloc >> 6);
        const int d    = dloc & 63;
        const int b    = m0 >> 11;
        const int sbase = (m0 & 2047) + half2_ * 64;
        const float bvv = bias[n0 + dloc];
        const size_t vb = ((size_t)(b * HEADS + h) * HD + d) * SEQ + sbase;
#pragma unroll
        for (int jj = 0; jj < 8; jj++) {
            uint32_t hw[4];
#pragma unroll
            for (int j2 = 0; j2 < 4; j2++) {
                const float f0 = es[(half2_ * 64 + jj * 8 + 2 * j2)     * EPI_LD + dloc] + bvv;
                const float f1 = es[(half2_ * 64 + jj * 8 + 2 * j2 + 1) * EPI_LD + dloc] + bvv;
                hw[j2] = pack_f16x2(f0, f1);
            }
            *reinterpret_cast<uint4*>(g_vth + vb + jj * 8) =
                make_uint4(hw[0], hw[1], hw[2], hw[3]);
        }
    }
}

// ---------------------------------------------------------------------------
// Tensor-core flash attention, fp16 single. grid=(SEQ/128, B*H), 8 warps.
// smem: double-buffered {K, Vt}, each 64 rows x 72-elem stride.
// ---------------------------------------------------------------------------
#define AK_STR   72
#define ATILE_EL (64 * AK_STR)
#define ABUF_EL  (2 * ATILE_EL)
#define AT_SMEM  (2 * ABUF_EL * 2)      // 36864 bytes

__device__ __forceinline__ void attn_stage(uint32_t sb, int buf, int kb,
                                           size_t hbase, size_t vbase, int tid)
{
#pragma unroll
    for (int i = 0; i < 4; i++) {
        const int t  = i >> 1;                     // 0=K, 1=V
        const int r  = (tid >> 3) + 32 * (i & 1);  // 0..63
        const int ch = tid & 7;
        const __half* src = (t == 0)
            ? g_kh  + hbase + (size_t)(kb * 64 + r) * HD + ch * 8
            : g_vth + vbase + (size_t)r * SEQ + kb * 64 + ch * 8;
        cp_async16(sb + (buf * ABUF_EL + t * ATILE_EL + r * AK_STR + ch * 8) * 2, src);
    }
}

__global__ __launch_bounds__(256)
void attn_mma()
{
    extern __shared__ __align__(16) __half sk[];
    const uint32_t sb = smem_u32(sk);
    const int tid  = threadIdx.x;
    const int wid  = tid >> 5;
    const int lane = tid & 31;
    const int gid  = lane >> 2;
    const int tidg = lane & 3;
    const int qb   = blockIdx.x;
    const int head = blockIdx.y;

    const size_t hbase = (size_t)head * SEQ * HD;
    const size_t vbase = (size_t)head * HD * SEQ;

    uint32_t qah[4][4];
    {
        const int r0 = qb * 128 + wid * 16 + gid;
        const uint32_t* q0h = reinterpret_cast<const uint32_t*>(g_qh + hbase + (size_t)r0 * HD);
        const uint32_t* q1h = reinterpret_cast<const uint32_t*>(g_qh + hbase + (size_t)(r0 + 8) * HD);
#pragma unroll
        for (int ks = 0; ks < 4; ks++) {
            qah[ks][0] = q0h[ks * 8 + tidg];
            qah[ks][1] = q1h[ks * 8 + tidg];
            qah[ks][2] = q0h[ks * 8 + tidg + 4];
            qah[ks][3] = q1h[ks * 8 + tidg + 4];
        }
    }

    float o[8][4];
#pragma unroll
    for (int nt = 0; nt < 8; nt++)
#pragma unroll
        for (int j = 0; j < 4; j++) o[nt][j] = 0.0f;
    float m0 = -1e30f, m1 = -1e30f, l0 = 0.0f, l1 = 0.0f;

    attn_stage(sb, 0, 0, hbase, vbase, tid);
    cp_commit();

    const int NKB = SEQ / 64;
    for (int kb = 0; kb < NKB; kb++) {
        if (kb + 1 < NKB) {
            attn_stage(sb, (kb + 1) & 1, kb + 1, hbase, vbase, tid);
            cp_commit();
            cp_wait<1>();
        } else {
            cp_wait<0>();
        }
        __syncthreads();

        const __half* bs = sk + (kb & 1) * ABUF_EL;
        const __half* Kh = bs;
        const __half* Vh = bs + ATILE_EL;

        float s[8][4];
#pragma unroll
        for (int nt = 0; nt < 8; nt++)
#pragma unroll
            for (int j = 0; j < 4; j++) s[nt][j] = 0.0f;

#pragma unroll
        for (int ks = 0; ks < 4; ks++) {
#pragma unroll
            for (int nt = 0; nt < 8; nt++) {
                const uint32_t* krh = reinterpret_cast<const uint32_t*>(
                    Kh + (nt * 8 + gid) * AK_STR);
                mma16816(s[nt], qah[ks], krh[8 * ks + tidg], krh[8 * ks + tidg + 4]);
            }
        }

        float mx0 = -1e30f, mx1 = -1e30f;
#pragma unroll
        for (int nt = 0; nt < 8; nt++) {
            mx0 = fmaxf(mx0, fmaxf(s[nt][0], s[nt][1]));
            mx1 = fmaxf(mx1, fmaxf(s[nt][2], s[nt][3]));
        }
        mx0 = fmaxf(mx0, __shfl_xor_sync(0xffffffffu, mx0, 1));
        mx0 = fmaxf(mx0, __shfl_xor_sync(0xffffffffu, mx0, 2));
        mx1 = fmaxf(mx1, __shfl_xor_sync(0xffffffffu, mx1, 1));
        mx1 = fmaxf(mx1, __shfl_xor_sync(0xffffffffu, mx1, 2));
        const float mn0 = fmaxf(m0, mx0), mn1 = fmaxf(m1, mx1);
        const float c0 = __expf(m0 - mn0), c1 = __expf(m1 - mn1);
        float rs0 = 0.0f, rs1 = 0.0f;
#pragma unroll
        for (int nt = 0; nt < 8; nt++) {
            s[nt][0] = __expf(s[nt][0] - mn0);
            s[nt][1] = __expf(s[nt][1] - mn0);
            s[nt][2] = __expf(s[nt][2] - mn1);
            s[nt][3] = __expf(s[nt][3] - mn1);
            rs0 += s[nt][0] + s[nt][1];
            rs1 += s[nt][2] + s[nt][3];
        }
        rs0 += __shfl_xor_sync(0xffffffffu, rs0, 1);
        rs0 += __shfl_xor_sync(0xffffffffu, rs0, 2);
        rs1 += __shfl_xor_sync(0xffffffffu, rs1, 1);
        rs1 += __shfl_xor_sync(0xffffffffu, rs1, 2);
        l0 = l0 * c0 + rs0;  l1 = l1 * c1 + rs1;
        m0 = mn0;  m1 = mn1;
#pragma unroll
        for (int nt = 0; nt < 8; nt++) {
            o[nt][0] *= c0; o[nt][1] *= c0;
            o[nt][2] *= c1; o[nt][3] *= c1;
        }

#pragma unroll
        for (int ks = 0; ks < 4; ks++) {
            uint32_t pah[4];
            pah[0] = pack_f16x2(s[2 * ks][0], s[2 * ks][1]);
            pah[1] = pack_f16x2(s[2 * ks][2], s[2 * ks][3]);
            pah[2] = pack_f16x2(s[2 * ks + 1][0], s[2 * ks + 1][1]);
            pah[3] = pack_f16x2(s[2 * ks + 1][2], s[2 * ks + 1][3]);
#pragma unroll
            for (int nt = 0; nt < 8; nt++) {
                const uint32_t* vrh = reinterpret_cast<const uint32_t*>(
                    Vh + (nt * 8 + gid) * AK_STR);
                mma16816(o[nt], pah, vrh[8 * ks + tidg], vrh[8 * ks + tidg + 4]);
            }
        }
        __syncthreads();
    }

    const float i0 = 1.0f / l0, i1 = 1.0f / l1;
    const int b = head >> 4, h = head & 15;
    const int s0 = qb * 128 + wid * 16;
#pragma unroll
    for (int nt = 0; nt < 8; nt++) {
        const float f0 = o[nt][0] * i0, f1 = o[nt][1] * i0;
        const float f2 = o[nt][2] * i1, f3 = o[nt][3] * i1;
        const size_t base0 = (size_t)(b * SEQ + s0 + gid) * EMB +
                             h * 64 + nt * 8 + 2 * tidg;
        const size_t base1 = (size_t)(b * SEQ + s0 + gid + 8) * EMB +
                             h * 64 + nt * 8 + 2 * tidg;
        *reinterpret_cast<uint32_t*>(g_aoh + base0) = pack_f16x2(f0, f1);
        *reinterpret_cast<uint32_t*>(g_aoh + base1) = pack_f16x2(f2, f3);
    }
}

// ---------------------------------------------------------------------------
extern "C" void kernel_launch(void* const* d_in, const int* in_sizes, int n_in,
                              void* d_out, int out_size)
{
    const float* hidden = (const float*)d_in[0];
    const float* qkv_w  = (const float*)d_in[1];
    const float* qkv_b  = (const float*)d_in[2];
    const float* proj_w = (const float*)d_in[3];
    const float* proj_b = (const float*)d_in[4];
    float* out = (float*)d_out;

    // 0) cos/sin table + fp32 -> fp16 conversions
    costab_kernel<<<(SEQ * 32 + 255) / 256, 256>>>();
    split_kernel<0><<<(MROWS * EMB / 4 + 255) / 256, 256>>>(hidden, MROWS * EMB / 4);
    split_kernel<1><<<(QKVN * EMB / 4 + 255) / 256, 256>>>(qkv_w, QKVN * EMB / 4);
    split_kernel<2><<<(EMB * EMB / 4 + 255) / 256, 256>>>(proj_w, EMB * EMB / 4);

    // 1) QKV GEMM (fp16 raw-mma, 4-stage) + fused RoPE/V-transpose epilogue
    cudaFuncSetAttribute(gemm_mma<1>,
                         cudaFuncAttributeMaxDynamicSharedMemorySize, GSMEM);
    gemm_mma<1><<<dim3(QKVN / 128, MROWS / 128), 256, GSMEM>>>(qkv_b, nullptr);

    // 2) tensor-core flash attention (fp16)
    cudaFuncSetAttribute(attn_mma,
                         cudaFuncAttributeMaxDynamicSharedMemorySize, AT_SMEM);
    attn_mma<<<dim3(SEQ / 128, BATCH * HEADS), 256, AT_SMEM>>>();

    // 3) output projection
    cudaFuncSetAttribute(gemm_mma<2>,
                         cudaFuncAttributeMaxDynamicSharedMemorySize, GSMEM);
    gemm_mma<2><<<dim3(EMB / 128, MROWS / 128), 256, GSMEM>>>(proj_b, out);
}

// round 16
// speedup vs baseline: 2.9898x; 1.0656x over previous
#include <cuda_runtime.h>
#include <cuda_fp16.h>
#include <math.h>
#include <stdint.h>

// Problem constants
#define BATCH 4
#define SEQ   2048
#define EMB   1024
#define HEADS 16
#define HD    64
#define MROWS (BATCH * SEQ)          // 8192
#define QKVN  (3 * EMB)              // 3072

// ---------------------------------------------------------------------------
// Device-global scratch (fp16 single precision operands)
// ---------------------------------------------------------------------------
__device__ __half g_ah[MROWS * EMB];      // hidden
__device__ __half g_wh[QKVN * EMB];       // qkv_w
__device__ __half g_ph[EMB * EMB];        // proj_w
__device__ __half g_aoh[MROWS * EMB];     // attn out

__device__ __half g_qh[BATCH * HEADS * SEQ * HD];
__device__ __half g_kh[BATCH * HEADS * SEQ * HD];
__device__ __half g_vth[BATCH * HEADS * HD * SEQ];   // [B,H,hd,S]

__device__ float g_cos[SEQ * 32], g_sin[SEQ * 32];

// ---------------------------------------------------------------------------
// helpers
// ---------------------------------------------------------------------------
__device__ __forceinline__ uint32_t smem_u32(const void* p) {
    uint32_t a;
    asm("{ .reg .u64 t; cvta.to.shared.u64 t, %1; cvt.u32.u64 %0, t; }"
        : "=r"(a) : "l"(p));
    return a;
}
__device__ __forceinline__ void cp_async16(uint32_t dst, const void* src) {
    asm volatile("cp.async.cg.shared.global [%0], [%1], 16;"
                 :: "r"(dst), "l"(src) : "memory");
}
__device__ __forceinline__ void cp_commit() {
    asm volatile("cp.async.commit_group;" ::: "memory");
}
template <int N>
__device__ __forceinline__ void cp_wait() {
    asm volatile("cp.async.wait_group %0;" :: "n"(N) : "memory");
}
__device__ __forceinline__ void ldsm4(uint32_t* r, uint32_t addr) {
    asm volatile("ldmatrix.sync.aligned.m8n8.x4.shared.b16 {%0,%1,%2,%3}, [%4];"
        : "=r"(r[0]), "=r"(r[1]), "=r"(r[2]), "=r"(r[3]) : "r"(addr));
}
// D += A*B, m16n8k16 row.col fp16 -> f32
__device__ __forceinline__ void mma16816(float* d, const uint32_t* a,
                                         uint32_t b0, uint32_t b1) {
    asm volatile(
        "mma.sync.aligned.m16n8k16.row.col.f32.f16.f16.f32 "
        "{%0,%1,%2,%3}, {%4,%5,%6,%7}, {%8,%9}, {%0,%1,%2,%3};"
        : "+f"(d[0]), "+f"(d[1]), "+f"(d[2]), "+f"(d[3])
        : "r"(a[0]), "r"(a[1]), "r"(a[2]), "r"(a[3]), "r"(b0), "r"(b1));
}
// pack two f32 into f16x2 (first arg in low half)
__device__ __forceinline__ uint32_t pack_f16x2(float lo, float hi) {
    uint32_t r;
    asm("cvt.rn.f16x2.f32 %0, %1, %2;" : "=r"(r) : "f"(hi), "f"(lo));
    return r;
}

// ---------------------------------------------------------------------------
// RoPE cos/sin table
// ---------------------------------------------------------------------------
__global__ __launch_bounds__(256)
void costab_kernel()
{
    const int i = blockIdx.x * 256 + threadIdx.x;
    if (i >= SEQ * 32) return;
    const int s = i >> 5, j = i & 31;
    const float invf = powf(10000.0f, -(float)(2 * j) / 64.0f);
    float c, sn;
    sincosf((float)s * invf, &sn, &c);
    g_cos[i] = c;
    g_sin[i] = sn;
}

// ---------------------------------------------------------------------------
// fp32 -> fp16 conversion.  WHICH: 0=hidden 1=qkv_w 2=proj_w
// ---------------------------------------------------------------------------
template <int WHICH>
__global__ __launch_bounds__(256)
void split_kernel(const float* __restrict__ x, int n4)
{
    __half* hi = (WHICH == 0) ? g_ah : (WHICH == 1) ? g_wh : g_ph;
    int i = blockIdx.x * 256 + threadIdx.x;
    if (i >= n4) return;
    float4 v = reinterpret_cast<const float4*>(x)[i];
    uint2 o;
    o.x = pack_f16x2(v.x, v.y);
    o.y = pack_f16x2(v.z, v.w);
    *(reinterpret_cast<uint2*>(hi) + i) = o;
}

// ---------------------------------------------------------------------------
// Raw-mma fp16 GEMM (unchanged from R15). CTA 128x128, BK=32, 4-stage.
// ---------------------------------------------------------------------------
#define BK       32
#define ROW_B    64
#define TILE_B   (128 * ROW_B)
#define STAGE_B  (2 * TILE_B)
#define NSTAGE   4
#define GSMEM    69632
#define EPI_LD   132

__device__ __forceinline__ uint32_t swz_off(int row, int chunk) {
    return (uint32_t)(row * ROW_B + ((chunk ^ ((row >> 1) & 3)) << 4));
}

__device__ __forceinline__ void cp_chunk(
    uint32_t sbuf, int c, int tid,
    const __half* A, const __half* B, int m0, int n0)
{
    const int k0 = c * BK;
#pragma unroll
    for (int t = 0; t < 2; t++) {
        const int row0 = (t == 0) ? m0 : n0;
        const __half* src = (t == 0) ? A : B;
#pragma unroll
        for (int i = 0; i < 2; i++) {
            const int idx = tid + i * 256;
            const int r   = idx >> 2;
            const int seg = idx & 3;
            cp_async16(sbuf + t * TILE_B + swz_off(r, seg),
                       src + (size_t)(row0 + r) * EMB + k0 + seg * 8);
        }
    }
}

template <int MODE>
__global__ __launch_bounds__(256, 2)
void gemm_mma(const float* __restrict__ bias, float* __restrict__ C)
{
    extern __shared__ __align__(16) char smem[];
    const int tid  = threadIdx.x;
    const int wid  = tid >> 5;
    const int lane = tid & 31;
    const int gid  = lane >> 2;
    const int tidg = lane & 3;
    const int m0 = blockIdx.y * 128;
    const int n0 = blockIdx.x * 128;

    const __half* A = (MODE == 1) ? g_ah : g_aoh;
    const __half* B = (MODE == 1) ? g_wh : g_ph;

    const int warp_m = (wid & 3) * 32;
    const int warp_n = (wid >> 2) * 64;

    const int arow_b = warp_m + (lane & 15);
    const int acsel  = lane >> 4;
    const int brow_b = warp_n + (lane & 7) + 8 * (lane >> 4);
    const int bcsel  = (lane >> 3) & 1;

    float acc[2][8][4];
#pragma unroll
    for (int mt = 0; mt < 2; mt++)
#pragma unroll
        for (int nn = 0; nn < 8; nn++)
#pragma unroll
            for (int j = 0; j < 4; j++) acc[mt][nn][j] = 0.0f;

    const uint32_t sb = smem_u32(smem);
    cp_chunk(sb,               0, tid, A, B, m0, n0); cp_commit();
    cp_chunk(sb + STAGE_B,     1, tid, A, B, m0, n0); cp_commit();
    cp_chunk(sb + 2 * STAGE_B, 2, tid, A, B, m0, n0); cp_commit();

    const int NCH = EMB / BK;
    int stage = 0;
    for (int c = 0; c < NCH; c++) {
        if (c + 3 < NCH) {
            int ps = stage + 3; if (ps >= NSTAGE) ps -= NSTAGE;
            cp_chunk(sb + ps * STAGE_B, c + 3, tid, A, B, m0, n0);
            cp_commit();
            cp_wait<3>();
        } else if (c + 2 < NCH) {
            cp_wait<2>();
        } else if (c + 1 < NCH) {
            cp_wait<1>();
        } else {
            cp_wait<0>();
        }
        __syncthreads();

        const uint32_t abase = sb + stage * STAGE_B;
        const uint32_t bbase = abase + TILE_B;

#pragma unroll
        for (int ks2 = 0; ks2 < 2; ks2++) {
            const int ccA = 2 * ks2 + acsel;
            const int ccB = 2 * ks2 + bcsel;

            uint32_t ah[2][4];
#pragma unroll
            for (int mt = 0; mt < 2; mt++)
                ldsm4(ah[mt], abase + swz_off(arow_b + mt * 16, ccA));

#pragma unroll
            for (int g = 0; g < 2; g++) {
                uint32_t bh[2][4];
#pragma unroll
                for (int np2 = 0; np2 < 2; np2++)
                    ldsm4(bh[np2], bbase + swz_off(brow_b + (2 * g + np2) * 16, ccB));
#pragma unroll
                for (int np2 = 0; np2 < 2; np2++)
#pragma unroll
                    for (int mt = 0; mt < 2; mt++) {
                        const int nn = (2 * g + np2) * 2;
                        mma16816(acc[mt][nn],     ah[mt], bh[np2][0], bh[np2][1]);
                        mma16816(acc[mt][nn + 1], ah[mt], bh[np2][2], bh[np2][3]);
                    }
            }
        }
        __syncthreads();
        if (++stage == NSTAGE) stage = 0;
    }

    float* es = reinterpret_cast<float*>(smem);
#pragma unroll
    for (int mt = 0; mt < 2; mt++)
#pragma unroll
        for (int nn = 0; nn < 8; nn++) {
            const int col = warp_n + nn * 8 + 2 * tidg;
            const int r0  = warp_m + mt * 16 + gid;
            *reinterpret_cast<float2*>(&es[r0 * EPI_LD + col]) =
                make_float2(acc[mt][nn][0], acc[mt][nn][1]);
            *reinterpret_cast<float2*>(&es[(r0 + 8) * EPI_LD + col]) =
                make_float2(acc[mt][nn][2], acc[mt][nn][3]);
        }
    __syncthreads();

    if (MODE == 2) {
#pragma unroll
        for (int i = 0; i < 16; i++) {
            const int idx  = tid + i * 256;
            const int row  = idx >> 5;
            const int col4 = idx & 31;
            const int m = m0 + row;
            const int n = n0 + col4 * 4;
            const float4 bv = *reinterpret_cast<const float4*>(bias + n);
            float4 v;
            v.x = es[row * EPI_LD + col4 * 4 + 0] + bv.x;
            v.y = es[row * EPI_LD + col4 * 4 + 1] + bv.y;
            v.z = es[row * EPI_LD + col4 * 4 + 2] + bv.z;
            v.w = es[row * EPI_LD + col4 * 4 + 3] + bv.w;
            *reinterpret_cast<float4*>(&C[(size_t)m * EMB + n]) = v;
        }
        return;
    }

    // ---- MODE 1 fused epilogue ----
    const int part = n0 >> 10;           // 0=q 1=k 2=v
    if (part < 2) {
        __half* dh = part ? g_kh : g_qh;
        const float qscale = part ? 1.0f : 0.125f;
#pragma unroll
        for (int i = 0; i < 16; i++) {
            const int idx  = tid + i * 256;
            const int row  = idx >> 5;
            const int col4 = idx & 31;
            const int cc   = col4 * 4;
            const int n    = n0 + cc;
            const int m    = m0 + row;
            const int h    = (n & 1023) >> 6;
            const int d    = n & 63;
            const int b    = m >> 11, s = m & 2047;
            const int dp   = d & 31;

            const float4 bv  = *reinterpret_cast<const float4*>(bias + n);
            const float4 bvp = *reinterpret_cast<const float4*>(bias + (n ^ 32));
            const float4 cv  = *reinterpret_cast<const float4*>(g_cos + s * 32 + dp);
            const float4 sv  = *reinterpret_cast<const float4*>(g_sin + s * 32 + dp);
            const float bvx[4]  = {bv.x, bv.y, bv.z, bv.w};
            const float bvpx[4] = {bvp.x, bvp.y, bvp.z, bvp.w};
            const float cvx[4]  = {cv.x, cv.y, cv.z, cv.w};
            const float svx[4]  = {sv.x, sv.y, sv.z, sv.w};

            const float sgn = (d < 32) ? -1.0f : 1.0f;
            uint32_t hw[2];
#pragma unroll
            for (int p2 = 0; p2 < 2; p2++) {
                float f[2];
#pragma unroll
                for (int q2 = 0; q2 < 2; q2++) {
                    const int j2 = p2 * 2 + q2;
                    const float x  = es[row * EPI_LD + cc + j2] + bvx[j2];
                    const float xp = es[row * EPI_LD + ((cc + j2) ^ 32)] + bvpx[j2];
                    f[q2] = (x * cvx[j2] + sgn * xp * svx[j2]) * qscale;
                }
                hw[p2] = pack_f16x2(f[0], f[1]);
            }
            const size_t base = ((size_t)(b * HEADS + h) * SEQ + s) * HD + d;
            *reinterpret_cast<uint2*>(dh + base) = make_uint2(hw[0], hw[1]);
        }
    } else {
        const int dloc = tid & 127;
        const int half2_ = tid >> 7;
        const int h    = ((n0 & 1023) >> 6) + (dloc >> 6);
        const int d    = dloc & 63;
        const int b    = m0 >> 11;
        const int sbase = (m0 & 2047) + half2_ * 64;
        const float bvv = bias[n0 + dloc];
        const size_t vb = ((size_t)(b * HEADS + h) * HD + d) * SEQ + sbase;
#pragma unroll
        for (int jj = 0; jj < 8; jj++) {
            uint32_t hw[4];
#pragma unroll
            for (int j2 = 0; j2 < 4; j2++) {
                const float f0 = es[(half2_ * 64 + jj * 8 + 2 * j2)     * EPI_LD + dloc] + bvv;
                const float f1 = es[(half2_ * 64 + jj * 8 + 2 * j2 + 1) * EPI_LD + dloc] + bvv;
                hw[j2] = pack_f16x2(f0, f1);
            }
            *reinterpret_cast<uint4*>(g_vth + vb + jj * 8) =
                make_uint4(hw[0], hw[1], hw[2], hw[3]);
        }
    }
}

// ---------------------------------------------------------------------------
// Tensor-core flash attention, fp16, ldmatrix fragments.
// grid=(SEQ/128, B*H), 8 warps. smem: double-buffered {K, Vt} tiles,
// 64 rows x 128B each, XOR-swizzled (chunk c at c ^ (row&7)).
// ---------------------------------------------------------------------------
#define AROW_B    128                   // bytes per tile row (64 fp16)
#define ATILE_B   (64 * AROW_B)         // 8192 bytes
#define ABUF_B    (2 * ATILE_B)         // K + Vt = 16384
#define AT_SMEM   (2 * ABUF_B)          // 32768

__device__ __forceinline__ uint32_t aswz(int row, int chunk) {
    return (uint32_t)(row * AROW_B + ((chunk ^ (row & 7)) << 4));
}

__device__ __forceinline__ void attn_stage(uint32_t sb, int buf, int kb,
                                           size_t hbase, size_t vbase, int tid)
{
#pragma unroll
    for (int i = 0; i < 4; i++) {
        const int t   = i >> 1;                       // 0=K, 1=V
        const int idx = tid + (i & 1) * 256;          // 0..511
        const int r   = idx >> 3;                     // 0..63
        const int ch  = idx & 7;                      // 16B chunk
        const __half* src = (t == 0)
            ? g_kh  + hbase + (size_t)(kb * 64 + r) * HD + ch * 8
            : g_vth + vbase + (size_t)r * SEQ + kb * 64 + ch * 8;
        cp_async16(sb + buf * ABUF_B + t * ATILE_B + aswz(r, ch), src);
    }
}

__global__ __launch_bounds__(256)
void attn_mma()
{
    extern __shared__ __align__(16) __half sk[];
    const uint32_t sb = smem_u32(sk);
    const int tid  = threadIdx.x;
    const int wid  = tid >> 5;
    const int lane = tid & 31;
    const int gid  = lane >> 2;
    const int tidg = lane & 3;
    const int qb   = blockIdx.x;
    const int head = blockIdx.y;

    const size_t hbase = (size_t)head * SEQ * HD;
    const size_t vbase = (size_t)head * HD * SEQ;

    // B-operand ldmatrix lane addressing (same pattern as gemm_mma)
    const int brow  = (lane & 7) + 8 * (lane >> 4);
    const int bcsel = (lane >> 3) & 1;

    uint32_t qah[4][4];
    {
        const int r0 = qb * 128 + wid * 16 + gid;
        const uint32_t* q0h = reinterpret_cast<const uint32_t*>(g_qh + hbase + (size_t)r0 * HD);
        const uint32_t* q1h = reinterpret_cast<const uint32_t*>(g_qh + hbase + (size_t)(r0 + 8) * HD);
#pragma unroll
        for (int ks = 0; ks < 4; ks++) {
            qah[ks][0] = q0h[ks * 8 + tidg];
            qah[ks][1] = q1h[ks * 8 + tidg];
            qah[ks][2] = q0h[ks * 8 + tidg + 4];
            qah[ks][3] = q1h[ks * 8 + tidg + 4];
        }
    }

    float o[8][4];
#pragma unroll
    for (int nt = 0; nt < 8; nt++)
#pragma unroll
        for (int j = 0; j < 4; j++) o[nt][j] = 0.0f;
    float m0 = -1e30f, m1 = -1e30f, l0 = 0.0f, l1 = 0.0f;

    attn_stage(sb, 0, 0, hbase, vbase, tid);
    cp_commit();

    const int NKB = SEQ / 64;
    for (int kb = 0; kb < NKB; kb++) {
        if (kb + 1 < NKB) {
            attn_stage(sb, (kb + 1) & 1, kb + 1, hbase, vbase, tid);
            cp_commit();
            cp_wait<1>();
        } else {
            cp_wait<0>();
        }
        __syncthreads();

        const uint32_t kbase = sb + (kb & 1) * ABUF_B;
        const uint32_t vbase_s = kbase + ATILE_B;

        float s[8][4];
#pragma unroll
        for (int nt = 0; nt < 8; nt++)
#pragma unroll
            for (int j = 0; j < 4; j++) s[nt][j] = 0.0f;

        // ---- S = Q K^T : ldmatrix B-fragments from swizzled K tile ----
#pragma unroll
        for (int ks = 0; ks < 4; ks++) {
#pragma unroll
            for (int nt2 = 0; nt2 < 4; nt2++) {
                uint32_t bk[4];
                ldsm4(bk, kbase + aswz(brow + nt2 * 16, 2 * ks + bcsel));
                mma16816(s[2 * nt2],     qah[ks], bk[0], bk[1]);
                mma16816(s[2 * nt2 + 1], qah[ks], bk[2], bk[3]);
            }
        }

        // ---- online softmax ----
        float mx0 = -1e30f, mx1 = -1e30f;
#pragma unroll
        for (int nt = 0; nt < 8; nt++) {
            mx0 = fmaxf(mx0, fmaxf(s[nt][0], s[nt][1]));
            mx1 = fmaxf(mx1, fmaxf(s[nt][2], s[nt][3]));
        }
        mx0 = fmaxf(mx0, __shfl_xor_sync(0xffffffffu, mx0, 1));
        mx0 = fmaxf(mx0, __shfl_xor_sync(0xffffffffu, mx0, 2));
        mx1 = fmaxf(mx1, __shfl_xor_sync(0xffffffffu, mx1, 1));
        mx1 = fmaxf(mx1, __shfl_xor_sync(0xffffffffu, mx1, 2));
        const float mn0 = fmaxf(m0, mx0), mn1 = fmaxf(m1, mx1);
        const float c0 = __expf(m0 - mn0), c1 = __expf(m1 - mn1);
        float rs0 = 0.0f, rs1 = 0.0f;
#pragma unroll
        for (int nt = 0; nt < 8; nt++) {
            s[nt][0] = __expf(s[nt][0] - mn0);
            s[nt][1] = __expf(s[nt][1] - mn0);
            s[nt][2] = __expf(s[nt][2] - mn1);
            s[nt][3] = __expf(s[nt][3] - mn1);
            rs0 += s[nt][0] + s[nt][1];
            rs1 += s[nt][2] + s[nt][3];
        }
        rs0 += __shfl_xor_sync(0xffffffffu, rs0, 1);
        rs0 += __shfl_xor_sync(0xffffffffu, rs0, 2);
        rs1 += __shfl_xor_sync(0xffffffffu, rs1, 1);
        rs1 += __shfl_xor_sync(0xffffffffu, rs1, 2);
        l0 = l0 * c0 + rs0;  l1 = l1 * c1 + rs1;
        m0 = mn0;  m1 = mn1;
#pragma unroll
        for (int nt = 0; nt < 8; nt++) {
            o[nt][0] *= c0; o[nt][1] *= c0;
            o[nt][2] *= c1; o[nt][3] *= c1;
        }

        // ---- O += P V : ldmatrix B-fragments from swizzled Vt tile ----
#pragma unroll
        for (int ks = 0; ks < 4; ks++) {
            uint32_t pah[4];
            pah[0] = pack_f16x2(s[2 * ks][0], s[2 * ks][1]);
            pah[1] = pack_f16x2(s[2 * ks][2], s[2 * ks][3]);
            pah[2] = pack_f16x2(s[2 * ks + 1][0], s[2 * ks + 1][1]);
            pah[3] = pack_f16x2(s[2 * ks + 1][2], s[2 * ks + 1][3]);
#pragma unroll
            for (int nt2 = 0; nt2 < 4; nt2++) {
                uint32_t bv[4];
                ldsm4(bv, vbase_s + aswz(brow + nt2 * 16, 2 * ks + bcsel));
                mma16816(o[2 * nt2],     pah, bv[0], bv[1]);
                mma16816(o[2 * nt2 + 1], pah, bv[2], bv[3]);
            }
        }
        __syncthreads();
    }

    const float i0 = 1.0f / l0, i1 = 1.0f / l1;
    const int b = head >> 4, h = head & 15;
    const int s0 = qb * 128 + wid * 16;
#pragma unroll
    for (int nt = 0; nt < 8; nt++) {
        const float f0 = o[nt][0] * i0, f1 = o[nt][1] * i0;
        const float f2 = o[nt][2] * i1, f3 = o[nt][3] * i1;
        const size_t base0 = (size_t)(b * SEQ + s0 + gid) * EMB +
                             h * 64 + nt * 8 + 2 * tidg;
        const size_t base1 = (size_t)(b * SEQ + s0 + gid + 8) * EMB +
                             h * 64 + nt * 8 + 2 * tidg;
        *reinterpret_cast<uint32_t*>(g_aoh + base0) = pack_f16x2(f0, f1);
        *reinterpret_cast<uint32_t*>(g_aoh + base1) = pack_f16x2(f2, f3);
    }
}

// ---------------------------------------------------------------------------
extern "C" void kernel_launch(void* const* d_in, const int* in_sizes, int n_in,
                              void* d_out, int out_size)
{
    const float* hidden = (const float*)d_in[0];
    const float* qkv_w  = (const float*)d_in[1];
    const float* qkv_b  = (const float*)d_in[2];
    const float* proj_w = (const float*)d_in[3];
    const float* proj_b = (const float*)d_in[4];
    float* out = (float*)d_out;

    // 0) cos/sin table + fp32 -> fp16 conversions
    costab_kernel<<<(SEQ * 32 + 255) / 256, 256>>>();
    split_kernel<0><<<(MROWS * EMB / 4 + 255) / 256, 256>>>(hidden, MROWS * EMB / 4);
    split_kernel<1><<<(QKVN * EMB / 4 + 255) / 256, 256>>>(qkv_w, QKVN * EMB / 4);
    split_kernel<2><<<(EMB * EMB / 4 + 255) / 256, 256>>>(proj_w, EMB * EMB / 4);

    // 1) QKV GEMM (fp16 raw-mma, 4-stage) + fused RoPE/V-transpose epilogue
    cudaFuncSetAttribute(gemm_mma<1>,
                         cudaFuncAttributeMaxDynamicSharedMemorySize, GSMEM);
    gemm_mma<1><<<dim3(QKVN / 128, MROWS / 128), 256, GSMEM>>>(qkv_b, nullptr);

    // 2) tensor-core flash attention (fp16, ldmatrix)
    cudaFuncSetAttribute(attn_mma,
                         cudaFuncAttributeMaxDynamicSharedMemorySize, AT_SMEM);
    attn_mma<<<dim3(SEQ / 128, BATCH * HEADS), 256, AT_SMEM>>>();

    // 3) output projection
    cudaFuncSetAttribute(gemm_mma<2>,
                         cudaFuncAttributeMaxDynamicSharedMemorySize, GSMEM);
    gemm_mma<2><<<dim3(EMB / 128, MROWS / 128), 256, GSMEM>>>(proj_b, out);
}

// round 17
// speedup vs baseline: 3.0939x; 1.0348x over previous
#include <cuda_runtime.h>
#include <cuda_fp16.h>
#include <math.h>
#include <stdint.h>

// Problem constants
#define BATCH 4
#define SEQ   2048
#define EMB   1024
#define HEADS 16
#define HD    64
#define MROWS (BATCH * SEQ)          // 8192
#define QKVN  (3 * EMB)              // 3072

// ---------------------------------------------------------------------------
// Device-global scratch (fp16 operands)
// ---------------------------------------------------------------------------
__device__ __half g_ah[MROWS * EMB];      // hidden
__device__ __half g_wh[QKVN * EMB];       // qkv_w
__device__ __half g_ph[EMB * EMB];        // proj_w
__device__ __half g_aoh[MROWS * EMB];     // attn out

__device__ __half g_qh[BATCH * HEADS * SEQ * HD];
__device__ __half g_kh[BATCH * HEADS * SEQ * HD];
__device__ __half g_vth[BATCH * HEADS * HD * SEQ];   // [B,H,hd,S]

__device__ float g_cos[SEQ * 32], g_sin[SEQ * 32];

// ---------------------------------------------------------------------------
// helpers
// ---------------------------------------------------------------------------
__device__ __forceinline__ uint32_t smem_u32(const void* p) {
    uint32_t a;
    asm("{ .reg .u64 t; cvta.to.shared.u64 t, %1; cvt.u32.u64 %0, t; }"
        : "=r"(a) : "l"(p));
    return a;
}
__device__ __forceinline__ void cp_async16(uint32_t dst, const void* src) {
    asm volatile("cp.async.cg.shared.global [%0], [%1], 16;"
                 :: "r"(dst), "l"(src) : "memory");
}
__device__ __forceinline__ void cp_commit() {
    asm volatile("cp.async.commit_group;" ::: "memory");
}
template <int N>
__device__ __forceinline__ void cp_wait() {
    asm volatile("cp.async.wait_group %0;" :: "n"(N) : "memory");
}
__device__ __forceinline__ void ldsm4(uint32_t* r, uint32_t addr) {
    asm volatile("ldmatrix.sync.aligned.m8n8.x4.shared.b16 {%0,%1,%2,%3}, [%4];"
        : "=r"(r[0]), "=r"(r[1]), "=r"(r[2]), "=r"(r[3]) : "r"(addr));
}
// D += A*B, m16n8k16 row.col fp16 -> f32
__device__ __forceinline__ void mma16816(float* d, const uint32_t* a,
                                         uint32_t b0, uint32_t b1) {
    asm volatile(
        "mma.sync.aligned.m16n8k16.row.col.f32.f16.f16.f32 "
        "{%0,%1,%2,%3}, {%4,%5,%6,%7}, {%8,%9}, {%0,%1,%2,%3};"
        : "+f"(d[0]), "+f"(d[1]), "+f"(d[2]), "+f"(d[3])
        : "r"(a[0]), "r"(a[1]), "r"(a[2]), "r"(a[3]), "r"(b0), "r"(b1));
}
// pack two f32 into f16x2 (first arg in low half)
__device__ __forceinline__ uint32_t pack_f16x2(float lo, float hi) {
    uint32_t r;
    asm("cvt.rn.f16x2.f32 %0, %1, %2;" : "=r"(r) : "f"(hi), "f"(lo));
    return r;
}

// ---------------------------------------------------------------------------
// RoPE cos/sin table
// ---------------------------------------------------------------------------
__global__ __launch_bounds__(256)
void costab_kernel()
{
    const int i = blockIdx.x * 256 + threadIdx.x;
    if (i >= SEQ * 32) return;
    const int s = i >> 5, j = i & 31;
    const float invf = powf(10000.0f, -(float)(2 * j) / 64.0f);
    float c, sn;
    sincosf((float)s * invf, &sn, &c);
    g_cos[i] = c;
    g_sin[i] = sn;
}

// ---------------------------------------------------------------------------
// fp32 -> fp16 conversion.  WHICH: 0=hidden 1=qkv_w 2=proj_w
// ---------------------------------------------------------------------------
template <int WHICH>
__global__ __launch_bounds__(256)
void split_kernel(const float* __restrict__ x, int n4)
{
    __half* hi = (WHICH == 0) ? g_ah : (WHICH == 1) ? g_wh : g_ph;
    int i = blockIdx.x * 256 + threadIdx.x;
    if (i >= n4) return;
    float4 v = reinterpret_cast<const float4*>(x)[i];
    uint2 o;
    o.x = pack_f16x2(v.x, v.y);
    o.y = pack_f16x2(v.z, v.w);
    *(reinterpret_cast<uint2*>(hi) + i) = o;
}

// ---------------------------------------------------------------------------
// Raw-mma fp16 GEMM (unchanged). CTA 128x128, BK=32, 4-stage.
// ---------------------------------------------------------------------------
#define BK       32
#define ROW_B    64
#define TILE_B   (128 * ROW_B)
#define STAGE_B  (2 * TILE_B)
#define NSTAGE   4
#define GSMEM    69632
#define EPI_LD   132

__device__ __forceinline__ uint32_t swz_off(int row, int chunk) {
    return (uint32_t)(row * ROW_B + ((chunk ^ ((row >> 1) & 3)) << 4));
}

__device__ __forceinline__ void cp_chunk(
    uint32_t sbuf, int c, int tid,
    const __half* A, const __half* B, int m0, int n0)
{
    const int k0 = c * BK;
#pragma unroll
    for (int t = 0; t < 2; t++) {
        const int row0 = (t == 0) ? m0 : n0;
        const __half* src = (t == 0) ? A : B;
#pragma unroll
        for (int i = 0; i < 2; i++) {
            const int idx = tid + i * 256;
            const int r   = idx >> 2;
            const int seg = idx & 3;
            cp_async16(sbuf + t * TILE_B + swz_off(r, seg),
                       src + (size_t)(row0 + r) * EMB + k0 + seg * 8);
        }
    }
}

template <int MODE>
__global__ __launch_bounds__(256, 2)
void gemm_mma(const float* __restrict__ bias, float* __restrict__ C)
{
    extern __shared__ __align__(16) char smem[];
    const int tid  = threadIdx.x;
    const int wid  = tid >> 5;
    const int lane = tid & 31;
    const int gid  = lane >> 2;
    const int tidg = lane & 3;
    const int m0 = blockIdx.y * 128;
    const int n0 = blockIdx.x * 128;

    const __half* A = (MODE == 1) ? g_ah : g_aoh;
    const __half* B = (MODE == 1) ? g_wh : g_ph;

    const int warp_m = (wid & 3) * 32;
    const int warp_n = (wid >> 2) * 64;

    const int arow_b = warp_m + (lane & 15);
    const int acsel  = lane >> 4;
    const int brow_b = warp_n + (lane & 7) + 8 * (lane >> 4);
    const int bcsel  = (lane >> 3) & 1;

    float acc[2][8][4];
#pragma unroll
    for (int mt = 0; mt < 2; mt++)
#pragma unroll
        for (int nn = 0; nn < 8; nn++)
#pragma unroll
            for (int j = 0; j < 4; j++) acc[mt][nn][j] = 0.0f;

    const uint32_t sb = smem_u32(smem);
    cp_chunk(sb,               0, tid, A, B, m0, n0); cp_commit();
    cp_chunk(sb + STAGE_B,     1, tid, A, B, m0, n0); cp_commit();
    cp_chunk(sb + 2 * STAGE_B, 2, tid, A, B, m0, n0); cp_commit();

    const int NCH = EMB / BK;
    int stage = 0;
    for (int c = 0; c < NCH; c++) {
        if (c + 3 < NCH) {
            int ps = stage + 3; if (ps >= NSTAGE) ps -= NSTAGE;
            cp_chunk(sb + ps * STAGE_B, c + 3, tid, A, B, m0, n0);
            cp_commit();
            cp_wait<3>();
        } else if (c + 2 < NCH) {
            cp_wait<2>();
        } else if (c + 1 < NCH) {
            cp_wait<1>();
        } else {
            cp_wait<0>();
        }
        __syncthreads();

        const uint32_t abase = sb + stage * STAGE_B;
        const uint32_t bbase = abase + TILE_B;

#pragma unroll
        for (int ks2 = 0; ks2 < 2; ks2++) {
            const int ccA = 2 * ks2 + acsel;
            const int ccB = 2 * ks2 + bcsel;

            uint32_t ah[2][4];
#pragma unroll
            for (int mt = 0; mt < 2; mt++)
                ldsm4(ah[mt], abase + swz_off(arow_b + mt * 16, ccA));

#pragma unroll
            for (int g = 0; g < 2; g++) {
                uint32_t bh[2][4];
#pragma unroll
                for (int np2 = 0; np2 < 2; np2++)
                    ldsm4(bh[np2], bbase + swz_off(brow_b + (2 * g + np2) * 16, ccB));
#pragma unroll
                for (int np2 = 0; np2 < 2; np2++)
#pragma unroll
                    for (int mt = 0; mt < 2; mt++) {
                        const int nn = (2 * g + np2) * 2;
                        mma16816(acc[mt][nn],     ah[mt], bh[np2][0], bh[np2][1]);
                        mma16816(acc[mt][nn + 1], ah[mt], bh[np2][2], bh[np2][3]);
                    }
            }
        }
        __syncthreads();
        if (++stage == NSTAGE) stage = 0;
    }

    float* es = reinterpret_cast<float*>(smem);
#pragma unroll
    for (int mt = 0; mt < 2; mt++)
#pragma unroll
        for (int nn = 0; nn < 8; nn++) {
            const int col = warp_n + nn * 8 + 2 * tidg;
            const int r0  = warp_m + mt * 16 + gid;
            *reinterpret_cast<float2*>(&es[r0 * EPI_LD + col]) =
                make_float2(acc[mt][nn][0], acc[mt][nn][1]);
            *reinterpret_cast<float2*>(&es[(r0 + 8) * EPI_LD + col]) =
                make_float2(acc[mt][nn][2], acc[mt][nn][3]);
        }
    __syncthreads();

    if (MODE == 2) {
#pragma unroll
        for (int i = 0; i < 16; i++) {
            const int idx  = tid + i * 256;
            const int row  = idx >> 5;
            const int col4 = idx & 31;
            const int m = m0 + row;
            const int n = n0 + col4 * 4;
            const float4 bv = *reinterpret_cast<const float4*>(bias + n);
            float4 v;
            v.x = es[row * EPI_LD + col4 * 4 + 0] + bv.x;
            v.y = es[row * EPI_LD + col4 * 4 + 1] + bv.y;
            v.z = es[row * EPI_LD + col4 * 4 + 2] + bv.z;
            v.w = es[row * EPI_LD + col4 * 4 + 3] + bv.w;
            *reinterpret_cast<float4*>(&C[(size_t)m * EMB + n]) = v;
        }
        return;
    }

    // ---- MODE 1 fused epilogue ----
    const int part = n0 >> 10;           // 0=q 1=k 2=v
    if (part < 2) {
        __half* dh = part ? g_kh : g_qh;
        const float qscale = part ? 1.0f : 0.125f;
#pragma unroll
        for (int i = 0; i < 16; i++) {
            const int idx  = tid + i * 256;
            const int row  = idx >> 5;
            const int col4 = idx & 31;
            const int cc   = col4 * 4;
            const int n    = n0 + cc;
            const int m    = m0 + row;
            const int h    = (n & 1023) >> 6;
            const int d    = n & 63;
            const int b    = m >> 11, s = m & 2047;
            const int dp   = d & 31;

            const float4 bv  = *reinterpret_cast<const float4*>(bias + n);
            const float4 bvp = *reinterpret_cast<const float4*>(bias + (n ^ 32));
            const float4 cv  = *reinterpret_cast<const float4*>(g_cos + s * 32 + dp);
            const float4 sv  = *reinterpret_cast<const float4*>(g_sin + s * 32 + dp);
            const float bvx[4]  = {bv.x, bv.y, bv.z, bv.w};
            const float bvpx[4] = {bvp.x, bvp.y, bvp.z, bvp.w};
            const float cvx[4]  = {cv.x, cv.y, cv.z, cv.w};
            const float svx[4]  = {sv.x, sv.y, sv.z, sv.w};

            const float sgn = (d < 32) ? -1.0f : 1.0f;
            uint32_t hw[2];
#pragma unroll
            for (int p2 = 0; p2 < 2; p2++) {
                float f[2];
#pragma unroll
                for (int q2 = 0; q2 < 2; q2++) {
                    const int j2 = p2 * 2 + q2;
                    const float x  = es[row * EPI_LD + cc + j2] + bvx[j2];
                    const float xp = es[row * EPI_LD + ((cc + j2) ^ 32)] + bvpx[j2];
                    f[q2] = (x * cvx[j2] + sgn * xp * svx[j2]) * qscale;
                }
                hw[p2] = pack_f16x2(f[0], f[1]);
            }
            const size_t base = ((size_t)(b * HEADS + h) * SEQ + s) * HD + d;
            *reinterpret_cast<uint2*>(dh + base) = make_uint2(hw[0], hw[1]);
        }
    } else {
        const int dloc = tid & 127;
        const int half2_ = tid >> 7;
        const int h    = ((n0 & 1023) >> 6) + (dloc >> 6);
        const int d    = dloc & 63;
        const int b    = m0 >> 11;
        const int sbase = (m0 & 2047) + half2_ * 64;
        const float bvv = bias[n0 + dloc];
        const size_t vb = ((size_t)(b * HEADS + h) * HD + d) * SEQ + sbase;
#pragma unroll
        for (int jj = 0; jj < 8; jj++) {
            uint32_t hw[4];
#pragma unroll
            for (int j2 = 0; j2 < 4; j2++) {
                const float f0 = es[(half2_ * 64 + jj * 8 + 2 * j2)     * EPI_LD + dloc] + bvv;
                const float f1 = es[(half2_ * 64 + jj * 8 + 2 * j2 + 1) * EPI_LD + dloc] + bvv;
                hw[j2] = pack_f16x2(f0, f1);
            }
            *reinterpret_cast<uint4*>(g_vth + vb + jj * 8) =
                make_uint4(hw[0], hw[1], hw[2], hw[3]);
        }
    }
}

// ---------------------------------------------------------------------------
// Tensor-core flash attention, fp16, ldmatrix fragments, 3-stage ring,
// single sync per iteration, 2 CTAs/SM.  grid=(SEQ/128, B*H), 8 warps.
// ---------------------------------------------------------------------------
#define AROW_B    128                   // bytes per tile row (64 fp16)
#define ATILE_B   (64 * AROW_B)         // 8192 bytes
#define ABUF_B    (2 * ATILE_B)         // K + Vt = 16384
#define ANSTAGE   3
#define AT_SMEM   (ANSTAGE * ABUF_B)    // 49152

__device__ __forceinline__ uint32_t aswz(int row, int chunk) {
    return (uint32_t)(row * AROW_B + ((chunk ^ (row & 7)) << 4));
}

__device__ __forceinline__ void attn_stage(uint32_t sb, int buf, int kb,
                                           size_t hbase, size_t vbase, int tid)
{
#pragma unroll
    for (int i = 0; i < 4; i++) {
        const int t   = i >> 1;                       // 0=K, 1=V
        const int idx = tid + (i & 1) * 256;          // 0..511
        const int r   = idx >> 3;                     // 0..63
        const int ch  = idx & 7;                      // 16B chunk
        const __half* src = (t == 0)
            ? g_kh  + hbase + (size_t)(kb * 64 + r) * HD + ch * 8
            : g_vth + vbase + (size_t)r * SEQ + kb * 64 + ch * 8;
        cp_async16(sb + buf * ABUF_B + t * ATILE_B + aswz(r, ch), src);
    }
}

__global__ __launch_bounds__(256, 2)
void attn_mma()
{
    extern __shared__ __align__(16) __half sk[];
    const uint32_t sb = smem_u32(sk);
    const int tid  = threadIdx.x;
    const int wid  = tid >> 5;
    const int lane = tid & 31;
    const int gid  = lane >> 2;
    const int tidg = lane & 3;
    const int qb   = blockIdx.x;
    const int head = blockIdx.y;

    const size_t hbase = (size_t)head * SEQ * HD;
    const size_t vbase = (size_t)head * HD * SEQ;

    // B-operand ldmatrix lane addressing
    const int brow  = (lane & 7) + 8 * (lane >> 4);
    const int bcsel = (lane >> 3) & 1;

    uint32_t qah[4][4];
    {
        const int r0 = qb * 128 + wid * 16 + gid;
        const uint32_t* q0h = reinterpret_cast<const uint32_t*>(g_qh + hbase + (size_t)r0 * HD);
        const uint32_t* q1h = reinterpret_cast<const uint32_t*>(g_qh + hbase + (size_t)(r0 + 8) * HD);
#pragma unroll
        for (int ks = 0; ks < 4; ks++) {
            qah[ks][0] = q0h[ks * 8 + tidg];
            qah[ks][1] = q1h[ks * 8 + tidg];
            qah[ks][2] = q0h[ks * 8 + tidg + 4];
            qah[ks][3] = q1h[ks * 8 + tidg + 4];
        }
    }

    float o[8][4];
#pragma unroll
    for (int nt = 0; nt < 8; nt++)
#pragma unroll
        for (int j = 0; j < 4; j++) o[nt][j] = 0.0f;
    float m0 = -1e30f, m1 = -1e30f, l0 = 0.0f, l1 = 0.0f;

    attn_stage(sb, 0, 0, hbase, vbase, tid);
    cp_commit();
    attn_stage(sb, 1, 1, hbase, vbase, tid);
    cp_commit();

    const int NKB = SEQ / 64;     // 32
    int buf = 0;
    for (int kb = 0; kb < NKB; kb++) {
        if (kb + 1 < NKB) cp_wait<1>(); else cp_wait<0>();
        __syncthreads();
        // prefetch kb+2 into (buf+2)%3 — its previous readers (iter kb-1)
        // are past the sync above, so no WAR hazard; single sync per iter.
        if (kb + 2 < NKB) {
            int pb = buf + 2; if (pb >= ANSTAGE) pb -= ANSTAGE;
            attn_stage(sb, pb, kb + 2, hbase, vbase, tid);
            cp_commit();
        }

        const uint32_t kbase   = sb + buf * ABUF_B;
        const uint32_t vbase_s = kbase + ATILE_B;

        float s[8][4];
#pragma unroll
        for (int nt = 0; nt < 8; nt++)
#pragma unroll
            for (int j = 0; j < 4; j++) s[nt][j] = 0.0f;

        // ---- S = Q K^T ----
#pragma unroll
        for (int ks = 0; ks < 4; ks++) {
#pragma unroll
            for (int nt2 = 0; nt2 < 4; nt2++) {
                uint32_t bk[4];
                ldsm4(bk, kbase + aswz(brow + nt2 * 16, 2 * ks + bcsel));
                mma16816(s[2 * nt2],     qah[ks], bk[0], bk[1]);
                mma16816(s[2 * nt2 + 1], qah[ks], bk[2], bk[3]);
            }
        }

        // ---- online softmax ----
        float mx0 = -1e30f, mx1 = -1e30f;
#pragma unroll
        for (int nt = 0; nt < 8; nt++) {
            mx0 = fmaxf(mx0, fmaxf(s[nt][0], s[nt][1]));
            mx1 = fmaxf(mx1, fmaxf(s[nt][2], s[nt][3]));
        }
        mx0 = fmaxf(mx0, __shfl_xor_sync(0xffffffffu, mx0, 1));
        mx0 = fmaxf(mx0, __shfl_xor_sync(0xffffffffu, mx0, 2));
        mx1 = fmaxf(mx1, __shfl_xor_sync(0xffffffffu, mx1, 1));
        mx1 = fmaxf(mx1, __shfl_xor_sync(0xffffffffu, mx1, 2));
        const float mn0 = fmaxf(m0, mx0), mn1 = fmaxf(m1, mx1);
        const float c0 = __expf(m0 - mn0), c1 = __expf(m1 - mn1);
        float rs0 = 0.0f, rs1 = 0.0f;
#pragma unroll
        for (int nt = 0; nt < 8; nt++) {
            s[nt][0] = __expf(s[nt][0] - mn0);
            s[nt][1] = __expf(s[nt][1] - mn0);
            s[nt][2] = __expf(s[nt][2] - mn1);
            s[nt][3] = __expf(s[nt][3] - mn1);
            rs0 += s[nt][0] + s[nt][1];
            rs1 += s[nt][2] + s[nt][3];
        }
        rs0 += __shfl_xor_sync(0xffffffffu, rs0, 1);
        rs0 += __shfl_xor_sync(0xffffffffu, rs0, 2);
        rs1 += __shfl_xor_sync(0xffffffffu, rs1, 1);
        rs1 += __shfl_xor_sync(0xffffffffu, rs1, 2);
        l0 = l0 * c0 + rs0;  l1 = l1 * c1 + rs1;
        m0 = mn0;  m1 = mn1;
#pragma unroll
        for (int nt = 0; nt < 8; nt++) {
            o[nt][0] *= c0; o[nt][1] *= c0;
            o[nt][2] *= c1; o[nt][3] *= c1;
        }

        // ---- O += P V ----
#pragma unroll
        for (int ks = 0; ks < 4; ks++) {
            uint32_t pah[4];
            pah[0] = pack_f16x2(s[2 * ks][0], s[2 * ks][1]);
            pah[1] = pack_f16x2(s[2 * ks][2], s[2 * ks][3]);
            pah[2] = pack_f16x2(s[2 * ks + 1][0], s[2 * ks + 1][1]);
            pah[3] = pack_f16x2(s[2 * ks + 1][2], s[2 * ks + 1][3]);
#pragma unroll
            for (int nt2 = 0; nt2 < 4; nt2++) {
                uint32_t bv[4];
                ldsm4(bv, vbase_s + aswz(brow + nt2 * 16, 2 * ks + bcsel));
                mma16816(o[2 * nt2],     pah, bv[0], bv[1]);
                mma16816(o[2 * nt2 + 1], pah, bv[2], bv[3]);
            }
        }

        if (++buf == ANSTAGE) buf = 0;
    }

    const float i0 = 1.0f / l0, i1 = 1.0f / l1;
    const int b = head >> 4, h = head & 15;
    const int s0 = qb * 128 + wid * 16;
#pragma unroll
    for (int nt = 0; nt < 8; nt++) {
        const float f0 = o[nt][0] * i0, f1 = o[nt][1] * i0;
        const float f2 = o[nt][2] * i1, f3 = o[nt][3] * i1;
        const size_t base0 = (size_t)(b * SEQ + s0 + gid) * EMB +
                             h * 64 + nt * 8 + 2 * tidg;
        const size_t base1 = (size_t)(b * SEQ + s0 + gid + 8) * EMB +
                             h * 64 + nt * 8 + 2 * tidg;
        *reinterpret_cast<uint32_t*>(g_aoh + base0) = pack_f16x2(f0, f1);
        *reinterpret_cast<uint32_t*>(g_aoh + base1) = pack_f16x2(f2, f3);
    }
}

// ---------------------------------------------------------------------------
extern "C" void kernel_launch(void* const* d_in, const int* in_sizes, int n_in,
                              void* d_out, int out_size)
{
    const float* hidden = (const float*)d_in[0];
    const float* qkv_w  = (const float*)d_in[1];
    const float* qkv_b  = (const float*)d_in[2];
    const float* proj_w = (const float*)d_in[3];
    const float* proj_b = (const float*)d_in[4];
    float* out = (float*)d_out;

    // 0) cos/sin table + fp32 -> fp16 conversions
    costab_kernel<<<(SEQ * 32 + 255) / 256, 256>>>();
    split_kernel<0><<<(MROWS * EMB / 4 + 255) / 256, 256>>>(hidden, MROWS * EMB / 4);
    split_kernel<1><<<(QKVN * EMB / 4 + 255) / 256, 256>>>(qkv_w, QKVN * EMB / 4);
    split_kernel<2><<<(EMB * EMB / 4 + 255) / 256, 256>>>(proj_w, EMB * EMB / 4);

    // 1) QKV GEMM (fp16 raw-mma, 4-stage) + fused RoPE/V-transpose epilogue
    cudaFuncSetAttribute(gemm_mma<1>,
                         cudaFuncAttributeMaxDynamicSharedMemorySize, GSMEM);
    gemm_mma<1><<<dim3(QKVN / 128, MROWS / 128), 256, GSMEM>>>(qkv_b, nullptr);

    // 2) tensor-core flash attention (fp16, ldmatrix, 3-stage, occ 2)
    cudaFuncSetAttribute(attn_mma,
                         cudaFuncAttributeMaxDynamicSharedMemorySize, AT_SMEM);
    attn_mma<<<dim3(SEQ / 128, BATCH * HEADS), 256, AT_SMEM>>>();

    // 3) output projection
    cudaFuncSetAttribute(gemm_mma<2>,
                         cudaFuncAttributeMaxDynamicSharedMemorySize, GSMEM);
    gemm_mma<2><<<dim3(EMB / 128, MROWS / 128), 256, GSMEM>>>(proj_b, out);
}